// round 11
// baseline (speedup 1.0000x reference)
#include <cuda_runtime.h>
#include <cuda_fp16.h>
#include <cstdint>

#define NB   32
#define NL   1023
#define NS   1024
#define NH   256
#define NC2  512
#define NE   256
#define NM1  32768
#define NM2  32736

// ---------------- scratch ----------------------------------------------------
__device__ __half g_Gh [NM1 * NE];                 // embeddings fp16
__device__ __half g_Yh [NM2 * NC2];                // conv out fp16
__device__ __half g_Dh [NM2 * NH];                 // dec_attn fp16
__device__ __half g_SCh[(long)NM2 * NS];           // scores fp16
__device__ __half g_ATh[(long)NM2 * NS];           // attn probs fp16
__device__ __half g_CWh[NC2 * 1536], g_CWl[NC2 * 1536];  // conv_w 2-limb (FW prep)
__device__ __half g_AWT[NE * 3 * NC2];             // affine_w^T [h|l|h]
__device__ __half g_FWB[NC2 * 768];                // fused weight fp16
__device__ __half g_MWb[NC2 * NH];                 // map_w fp16
__device__ __half g_EAb[(long)NB * NS * NH];       // enc_attn fp16
__device__ __half g_SST[(long)NB * NC2 * NS];      // src_seq^T fp16 (b,d,s)
__device__ float  g_BC [3 * NC2];
__device__ float  g_BR [3 * NC2];

// ---------------- helpers ----------------------------------------------------
__device__ __forceinline__ uint32_t smem_u32(const void* p) {
    uint32_t a;
    asm("{ .reg .u64 t; cvta.to.shared.u64 t, %1; cvt.u32.u64 %0, t; }" : "=r"(a) : "l"(p));
    return a;
}
__device__ __forceinline__ void cpasync16(uint32_t s, const void* g, bool pred) {
    int sz = pred ? 16 : 0;
    asm volatile("cp.async.cg.shared.global [%0], [%1], 16, %2;\n" :: "r"(s), "l"(g), "r"(sz));
}
__device__ __forceinline__ void cp_commit() { asm volatile("cp.async.commit_group;\n" ::: "memory"); }

__device__ __forceinline__ void ldm4(uint32_t* r, uint32_t a) {
    asm volatile("ldmatrix.sync.aligned.m8n8.x4.shared.b16 {%0,%1,%2,%3}, [%4];"
                 : "=r"(r[0]), "=r"(r[1]), "=r"(r[2]), "=r"(r[3]) : "r"(a));
}
__device__ __forceinline__ void mma16816(float* c, const uint32_t* a, const uint32_t* b) {
    asm volatile(
        "mma.sync.aligned.m16n8k16.row.col.f32.f16.f16.f32 "
        "{%0,%1,%2,%3}, {%4,%5,%6,%7}, {%8,%9}, {%0,%1,%2,%3};"
        : "+f"(c[0]), "+f"(c[1]), "+f"(c[2]), "+f"(c[3])
        : "r"(a[0]), "r"(a[1]), "r"(a[2]), "r"(a[3]), "r"(b[0]), "r"(b[1]));
}
__device__ __forceinline__ void split2(float v, __half& h, __half& l) {
    h = __float2half(v);
    l = __float2half(v - __half2float(h));
}

// ---------------- mega prep kernel -------------------------------------------
#define PB_GATHER 0
#define PB_ENC    16384
#define PB_MAP    32768
#define PB_SPLIT  33024
#define PB_AWT    34560
#define PB_SST    34688
#define PB_BCONST 51072
#define PB_TOTAL  51264

__global__ void mega_prep(const int* __restrict__ target,
                          const float* __restrict__ emb,
                          const float* __restrict__ enc_attn,
                          const float* __restrict__ map_w,
                          const float* __restrict__ conv_w,
                          const float* __restrict__ affine_w,
                          const float* __restrict__ affine_b,
                          const float* __restrict__ src_seq) {
    const int bid = blockIdx.x;
    const int tid = threadIdx.x;

    if (bid < PB_ENC) {
        long gid = (long)(bid - PB_GATHER) * 256 + tid;
        int m = (int)(gid >> 7);
        int k = ((int)gid & 127) * 2;
        int b = m >> 10, t = m & 1023;
        int idx = target[t * NB + b];
        float2 v = *(const float2*)(emb + (long)idx * NE + k);
        __half2 hh; hh.x = __float2half(v.x); hh.y = __float2half(v.y);
        *(__half2*)(g_Gh + (long)m * NE + k) = hh;
    } else if (bid < PB_MAP) {
        long gid = (long)(bid - PB_ENC) * 256 + tid;
        float2 v = *(const float2*)(enc_attn + gid * 2);
        __half2 hh; hh.x = __float2half(v.x); hh.y = __float2half(v.y);
        *(__half2*)(g_EAb + gid * 2) = hh;
    } else if (bid < PB_SPLIT) {
        long gid = (long)(bid - PB_MAP) * 256 + tid;
        float2 v = *(const float2*)(map_w + gid * 2);
        __half2 hh; hh.x = __float2half(v.x); hh.y = __float2half(v.y);
        *(__half2*)(g_MWb + gid * 2) = hh;
    } else if (bid < PB_AWT) {
        long gid = (long)(bid - PB_SPLIT) * 256 + tid;
        float2 v = *(const float2*)(conv_w + gid * 2);
        __half h0, l0, h1, l1;
        split2(v.x, h0, l0); split2(v.y, h1, l1);
        __half2 hh; hh.x = h0; hh.y = h1;
        __half2 ll; ll.x = l0; ll.y = l1;
        *(__half2*)(g_CWh + gid * 2) = hh;
        *(__half2*)(g_CWl + gid * 2) = ll;
    } else if (bid < PB_SST) {
        __shared__ float tile[32][33];
        int lb = bid - PB_AWT;
        int i0 = (lb >> 3) * 32, e0 = (lb & 7) * 32;
        int tx = tid & 31, ty0 = tid >> 5;
        #pragma unroll
        for (int p = 0; p < 4; p++) {
            int ty = ty0 + p * 8;
            tile[ty][tx] = affine_w[(i0 + ty) * NE + e0 + tx];
        }
        __syncthreads();
        #pragma unroll
        for (int p = 0; p < 4; p++) {
            int ty = ty0 + p * 8;
            float v = tile[tx][ty];
            __half h, l; split2(v, h, l);
            long base = (long)(e0 + ty) * 1536 + i0 + tx;
            g_AWT[base] = h; g_AWT[base + 512] = l; g_AWT[base + 1024] = h;
        }
    } else if (bid < PB_BCONST) {
        __shared__ float tile[32][33];
        int lb = bid - PB_SST;
        int b = lb >> 9;
        int rem = lb & 511;
        int dy = rem >> 5, sx = rem & 31;
        int s0 = sx * 32, d0 = dy * 32;
        int tx = tid & 31, ty0 = tid >> 5;
        #pragma unroll
        for (int p = 0; p < 4; p++) {
            int ty = ty0 + p * 8;
            tile[ty][tx] = src_seq[((long)b * NS + s0 + ty) * NC2 + d0 + tx];
        }
        __syncthreads();
        #pragma unroll
        for (int p = 0; p < 4; p++) {
            int ty = ty0 + p * 8;
            g_SST[((long)b * NC2 + d0 + ty) * NS + s0 + tx] = __float2half(tile[tx][ty]);
        }
    } else {
        int wid = (bid - PB_BCONST) * 8 + (tid >> 5);
        int lane = tid & 31;
        int tap = wid / 512, o = wid % 512;
        const float* row = conv_w + (long)o * 1536 + tap * 512;
        float s = 0.f;
        for (int i = lane; i < 512; i += 32) s += row[i] * affine_b[i];
        #pragma unroll
        for (int off = 16; off > 0; off >>= 1) s += __shfl_xor_sync(~0u, s, off);
        if (lane == 0) g_BC[tap * 512 + o] = s;
    }
}

__global__ void biasrows_kernel(const float* __restrict__ conv_b) {
    int o = blockIdx.x * blockDim.x + threadIdx.x;
    if (o >= 512) return;
    float b = conv_b[o];
    float c0 = g_BC[o], c1 = g_BC[512 + o], c2 = g_BC[1024 + o];
    g_BR[o]        = b + c2;
    g_BR[512 + o]  = b + c1 + c2;
    g_BR[1024 + o] = b + c0 + c1 + c2;
}

// GLU: 2 rows per block, half2 loads
__global__ void glu_kernel() {
    int r  = threadIdx.x >> 7;
    int m  = blockIdx.x * 2 + r;
    int h2 = threadIdx.x & 127;
    const __half2* yrow = (const __half2*)(g_Yh + (long)m * NC2);
    __half2 a2 = yrow[h2];
    __half2 g2 = yrow[128 + h2];
    float a0 = fmaxf(__low2float(a2), 0.f), a1 = fmaxf(__high2float(a2), 0.f);
    float g0 = fmaxf(__low2float(g2), 0.f), g1 = fmaxf(__high2float(g2), 0.f);
    __shared__ float red[2][4];
    int lane = threadIdx.x & 31, wIn = (threadIdx.x >> 5) & 3;
    float v = fmaxf(g0, g1);
    #pragma unroll
    for (int o = 16; o > 0; o >>= 1) v = fmaxf(v, __shfl_xor_sync(~0u, v, o));
    if (lane == 0) red[r][wIn] = v;
    __syncthreads();
    float mx = fmaxf(fmaxf(red[r][0], red[r][1]), fmaxf(red[r][2], red[r][3]));
    float e0 = expf(g0 - mx), e1 = expf(g1 - mx);
    __syncthreads();
    v = e0 + e1;
    #pragma unroll
    for (int o = 16; o > 0; o >>= 1) v += __shfl_xor_sync(~0u, v, o);
    if (lane == 0) red[r][wIn] = v;
    __syncthreads();
    float sum = red[r][0] + red[r][1] + red[r][2] + red[r][3];
    float inv = 1.f / sum;
    __half2 d2; d2.x = __float2half(a0 * e0 * inv); d2.y = __float2half(a1 * e1 * inv);
    *(__half2*)(g_Dh + (long)m * NH + 2 * h2) = d2;
}

// softmax over fp16 scores -> fp16 probs
__global__ void softmax_rows_kernel() {
    int m = blockIdx.x;
    int h = threadIdx.x;
    const __half2* row = (const __half2*)(g_SCh + (long)m * NS);
    __half2 p0 = row[h];
    __half2 p1 = row[256 + h];
    float x0 = __low2float(p0), x1 = __high2float(p0);
    float x2 = __low2float(p1), x3 = __high2float(p1);
    __shared__ float red[8];
    float v = fmaxf(fmaxf(x0, x1), fmaxf(x2, x3));
    #pragma unroll
    for (int o = 16; o > 0; o >>= 1) v = fmaxf(v, __shfl_xor_sync(~0u, v, o));
    if ((h & 31) == 0) red[h >> 5] = v;
    __syncthreads();
    float mx = red[0];
    #pragma unroll
    for (int i = 1; i < 8; i++) mx = fmaxf(mx, red[i]);
    float e0 = expf(x0 - mx), e1 = expf(x1 - mx), e2 = expf(x2 - mx), e3 = expf(x3 - mx);
    __syncthreads();
    v = e0 + e1 + e2 + e3;
    #pragma unroll
    for (int o = 16; o > 0; o >>= 1) v += __shfl_xor_sync(~0u, v, o);
    if ((h & 31) == 0) red[h >> 5] = v;
    __syncthreads();
    float sum = 0.f;
    #pragma unroll
    for (int i = 0; i < 8; i++) sum += red[i];
    float inv = 1.f / sum;
    __half2* orow = (__half2*)(g_ATh + (long)m * NS);
    __half2 q0; q0.x = __float2half(e0 * inv); q0.y = __float2half(e1 * inv);
    __half2 q1; q1.x = __float2half(e2 * inv); q1.y = __float2half(e3 * inv);
    orow[h] = q0;
    orow[256 + h] = q1;
}

// ---------------- mma.sync fp16 GEMM: 512 thr, 16 warps, 32x32 warp tile -----
// Block tile 128x128, BK=32, 4-stage cp.async, occupancy 2 (32 warps/SM).
// AMODE 0: A rows; aBatch!=0 -> A pre-offset by z*aBatch, rows by l.
// AMODE 2: fused conv on G. AMODE 3: concat Dh|ATh. BCAT: B concat map_w|SST.
// NSEG 3: A=[Ahi|Ahi|Alo], B 3-seg (FW precompute).
// EPI: 0 f32+bias1D, 3 fp16 write, 5 fp16+bias2D BR[min(l,2)].
#define GEMM_SMEM (4 * 16384)

template <int AMODE, int EPI, int NSEG, bool BCAT>
__global__ __launch_bounds__(512, 2)
void gemm_mma(const __half* __restrict__ Ahi, const __half* __restrict__ Alo, long aBatch,
              int KB, int lda, const __half* __restrict__ Bm, long bBatch,
              const __half* __restrict__ B2,
              const float* __restrict__ bias,
              float* __restrict__ C, int cLd,
              __half* __restrict__ Ohi, long oBatch,
              int Mb) {
    extern __shared__ char smem[];
    const uint32_t sb = smem_u32(smem);
    const int tid = threadIdx.x;
    const int z  = blockIdx.z;
    const int l0 = blockIdx.y * 128;
    const int n0 = blockIdx.x * 128;
    const int Kp = NSEG * KB;
    const int NK = Kp / 32;
    const __half* Bb = Bm + (long)z * bBatch;
    Ahi += (long)z * aBatch;
    if (NSEG == 3) Alo += (long)z * aBatch;

    auto load_tile = [&](int kt, int st) {
        const int k0 = kt * 32;
        const uint32_t sA = sb + st * 16384;
        const uint32_t sB = sA + 8192;
        // A: 512 chunks of 16B, one per thread
        {
            const int seg = (NSEG == 3) ? (k0 / KB) : 0;
            const int rem0 = (NSEG == 3) ? (k0 - seg * KB) : k0;
            int m = tid >> 2, kc = tid & 3;
            int l = l0 + m;
            long g; bool ok; const __half* Ab;
            if (AMODE == 0) {
                ok = (l < Mb);
                long rowbase = aBatch ? (long)l : ((long)z * Mb + l);
                g = rowbase * (long)lda + rem0 + kc * 8;
                Ab = (NSEG == 3 && seg == 2) ? Alo : Ahi;
            } else if (AMODE == 2) {
                int tap = rem0 >> 8;
                int e = (rem0 & 255) + kc * 8;
                int t = l - 2 + tap;
                ok = (l < Mb) && (t >= 0);
                g = ((long)z * 1024 + t) * 256 + e;
                Ab = Ahi;
            } else {
                ok = (l < Mb);
                if (k0 < 256) { g = ((long)z * Mb + l) * 256 + k0 + kc * 8; Ab = Ahi; }
                else          { g = ((long)z * Mb + l) * 1024 + (k0 - 256) + kc * 8; Ab = Alo; }
            }
            cpasync16(sA + m * 64 + ((uint32_t)(kc ^ (m & 3)) << 4), Ab + (ok ? g : 0), ok);
        }
        // B: 512 chunks of 16B, one per thread
        {
            int n = tid >> 2, kc = tid & 3;
            const __half* src; long g;
            if (BCAT) {
                if (k0 < 256) { src = Bm; g = (long)(n0 + n) * 256 + k0 + kc * 8; }
                else { src = B2; g = ((long)z * 512 + n0 + n) * 1024 + (k0 - 256) + kc * 8; }
            } else {
                src = Bb; g = (long)(n0 + n) * Kp + k0 + kc * 8;
            }
            cpasync16(sB + n * 64 + ((uint32_t)(kc ^ (n & 3)) << 4), src + g, true);
        }
        cp_commit();
    };

    float acc[2][4][4];
    #pragma unroll
    for (int i = 0; i < 2; i++)
        #pragma unroll
        for (int j = 0; j < 4; j++)
            #pragma unroll
            for (int q = 0; q < 4; q++) acc[i][j][q] = 0.f;

    const int w = tid >> 5, lid = tid & 31;
    const int wm = w >> 2, wn = w & 3;          // warp grid 4 x 4
    const int rl = wm * 32 + (lid & 15);        // A ldmatrix row
    const int aC = lid >> 4;                    // A k-chunk bit
    const int nl = wn * 32 + ((lid >> 4) << 3) + (lid & 7);  // B ldmatrix row
    const int bC = (lid >> 3) & 1;              // B k-chunk bit

    load_tile(0, 0); load_tile(1, 1); load_tile(2, 2);

    for (int kt = 0; kt < NK; kt++) {
        const int st = kt & 3;
        asm volatile("cp.async.wait_group 2;\n" ::: "memory");
        __syncthreads();
        if (kt + 3 < NK) load_tile(kt + 3, (kt + 3) & 3);
        else cp_commit();

        const uint32_t sA = sb + st * 16384;
        const uint32_t sB = sA + 8192;
        #pragma unroll
        for (int ks = 0; ks < 2; ks++) {
            uint32_t a[2][4];
            #pragma unroll
            for (int i = 0; i < 2; i++) {
                int r = rl + i * 16;
                ldm4(a[i], sA + r * 64 + ((uint32_t)((ks * 2 + aC) ^ (r & 3)) << 4));
            }
            uint32_t b[4][2];
            #pragma unroll
            for (int jj = 0; jj < 2; jj++) {
                int n = nl + jj * 16;
                uint32_t t[4];
                ldm4(t, sB + n * 64 + ((uint32_t)((ks * 2 + bC) ^ (n & 3)) << 4));
                b[jj * 2][0] = t[0]; b[jj * 2][1] = t[1];
                b[jj * 2 + 1][0] = t[2]; b[jj * 2 + 1][1] = t[3];
            }
            #pragma unroll
            for (int i = 0; i < 2; i++)
                #pragma unroll
                for (int j = 0; j < 4; j++)
                    mma16816(acc[i][j], a[i], b[j]);
        }
    }

    // ---------------- epilogue ----------------
    const int g  = lid >> 2, t4 = lid & 3;
    __half* Op = Ohi + (long)z * oBatch;
    #pragma unroll
    for (int i = 0; i < 2; i++) {
        #pragma unroll
        for (int h = 0; h < 2; h++) {
            int row = l0 + wm * 32 + i * 16 + g + h * 8;
            if (row >= Mb) continue;
            long grow = (long)z * Mb + row;
            long orow = oBatch ? (long)row : grow;
            #pragma unroll
            for (int j = 0; j < 4; j++) {
                int col = n0 + wn * 32 + j * 8 + 2 * t4;
                float v0 = acc[i][j][h * 2 + 0];
                float v1 = acc[i][j][h * 2 + 1];
                if (EPI == 0) { v0 += bias[col]; v1 += bias[col + 1]; }
                if (EPI == 5) {
                    int jb = (row < 2) ? row : 2;
                    v0 += bias[jb * 512 + col]; v1 += bias[jb * 512 + col + 1];
                }
                if (EPI == 3 || EPI == 5) {
                    __half2 hh; hh.x = __float2half(v0); hh.y = __float2half(v1);
                    *(__half2*)(Op + orow * (long)cLd + col) = hh;
                } else {
                    float* cp = C + grow * (long)cLd + col;
                    float2 r; r.x = v0; r.y = v1;
                    *(float2*)cp = r;
                }
            }
        }
    }
}

// ---------------- launcher ---------------------------------------------------
extern "C" void kernel_launch(void* const* d_in, const int* in_sizes, int n_in,
                              void* d_out, int out_size) {
    const int*   target   = (const int*)d_in[1];
    const float* enc_attn = (const float*)d_in[2];
    const float* src_seq  = (const float*)d_in[3];
    const float* emb      = (const float*)d_in[4];
    const float* affine_w = (const float*)d_in[5];
    const float* affine_b = (const float*)d_in[6];
    const float* conv_w   = (const float*)d_in[7];
    const float* conv_b   = (const float*)d_in[8];
    const float* map_w    = (const float*)d_in[9];
    const float* map_b    = (const float*)d_in[10];
    float* out = (float*)d_out;

    __half *Gh, *Yh, *Dh, *SCh, *ATh, *CWh, *CWl, *AWT, *FWB, *MWb, *EAb, *SST;
    float *BR;
    cudaGetSymbolAddress((void**)&Gh,  g_Gh);
    cudaGetSymbolAddress((void**)&Yh,  g_Yh);
    cudaGetSymbolAddress((void**)&Dh,  g_Dh);
    cudaGetSymbolAddress((void**)&SCh, g_SCh);
    cudaGetSymbolAddress((void**)&ATh, g_ATh);
    cudaGetSymbolAddress((void**)&CWh, g_CWh);   cudaGetSymbolAddress((void**)&CWl, g_CWl);
    cudaGetSymbolAddress((void**)&AWT, g_AWT);   cudaGetSymbolAddress((void**)&FWB, g_FWB);
    cudaGetSymbolAddress((void**)&MWb, g_MWb);   cudaGetSymbolAddress((void**)&EAb, g_EAb);
    cudaGetSymbolAddress((void**)&SST, g_SST);   cudaGetSymbolAddress((void**)&BR,  g_BR);

    cudaFuncSetAttribute(gemm_mma<0, 3, 3, false>, cudaFuncAttributeMaxDynamicSharedMemorySize, GEMM_SMEM);
    cudaFuncSetAttribute(gemm_mma<2, 5, 1, false>, cudaFuncAttributeMaxDynamicSharedMemorySize, GEMM_SMEM);
    cudaFuncSetAttribute(gemm_mma<0, 3, 1, false>, cudaFuncAttributeMaxDynamicSharedMemorySize, GEMM_SMEM);
    cudaFuncSetAttribute(gemm_mma<3, 0, 1, true>,  cudaFuncAttributeMaxDynamicSharedMemorySize, GEMM_SMEM);

    // 1. all conversions / weight prep in one launch
    mega_prep<<<PB_TOTAL, 256>>>(target, emb, enc_attn, map_w, conv_w,
                                 affine_w, affine_b, src_seq);
    // 2. bias rows
    biasrows_kernel<<<2, 256>>>(conv_b);
    // 3. fused weight (3-term, batched over taps): FW_tap = conv_w[.,tap,:] @ AWT
    gemm_mma<0, 3, 3, false><<<dim3(2, 4, 3), 512, GEMM_SMEM>>>(
        CWh, CWl, 512, 512, 1536, AWT, 0, nullptr,
        nullptr, nullptr, 768, FWB, 256, 512);
    // 4. fused conv on G -> Yh fp16 (+bias rows)   (M=1023/b, N=512, K=768)
    gemm_mma<2, 5, 1, false><<<dim3(4, 8, NB), 512, GEMM_SMEM>>>(
        Gh, nullptr, 0, 768, 0, FWB, 0, nullptr, BR, nullptr, 512, Yh, 0, NL);
    // 5. GLU -> Dh
    glu_kernel<<<NM2 / 2, 256>>>();
    // 6. scores -> SCh fp16 (batched)              (N=1024, K=256)
    gemm_mma<0, 3, 1, false><<<dim3(8, 8, NB), 512, GEMM_SMEM>>>(
        Dh, nullptr, 0, 256, 256, EAb, (long)NS * NH, nullptr,
        nullptr, nullptr, NS, SCh, 0, NL);
    // 7. softmax -> ATh fp16
    softmax_rows_kernel<<<NM2, 256>>>();
    // 8. combined: out = [Dh|ATh] @ [map_w|SST]^T + map_b   (N=512, K=1280)
    gemm_mma<3, 0, 1, true><<<dim3(4, 8, NB), 512, GEMM_SMEM>>>(
        Dh, ATh, 0, 1280, 0, MWb, 0, SST, map_b, out, 512, nullptr, 0, NL);
}

// round 12
// speedup vs baseline: 1.1721x; 1.1721x over previous
#include <cuda_runtime.h>
#include <cuda_fp16.h>
#include <cstdint>

#define NB   32
#define NL   1023
#define NS   1024
#define NH   256
#define NC2  512
#define NE   256
#define NM1  32768
#define NM2  32736
#define PERSIST 296

// ---------------- scratch ----------------------------------------------------
__device__ __half g_Gh [NM1 * NE];
__device__ __half g_Yh [NM2 * NC2];
__device__ __half g_Dh [NM2 * NH];
__device__ __half g_SCh[(long)NM2 * NS];
__device__ __half g_ATh[(long)NM2 * NS];
__device__ __half g_CWh[NC2 * 1536], g_CWl[NC2 * 1536];
__device__ __half g_AWT[NE * 3 * NC2];
__device__ __half g_FWB[NC2 * 768];
__device__ __half g_MWb[NC2 * NH];
__device__ __half g_EAb[(long)NB * NS * NH];
__device__ __half g_SST[(long)NB * NC2 * NS];
__device__ float  g_BC [3 * NC2];
__device__ float  g_BR [3 * NC2];

// ---------------- helpers ----------------------------------------------------
__device__ __forceinline__ uint32_t smem_u32(const void* p) {
    uint32_t a;
    asm("{ .reg .u64 t; cvta.to.shared.u64 t, %1; cvt.u32.u64 %0, t; }" : "=r"(a) : "l"(p));
    return a;
}
__device__ __forceinline__ void cpasync16(uint32_t s, const void* g, bool pred) {
    int sz = pred ? 16 : 0;
    asm volatile("cp.async.cg.shared.global [%0], [%1], 16, %2;\n" :: "r"(s), "l"(g), "r"(sz));
}
__device__ __forceinline__ void cp_commit() { asm volatile("cp.async.commit_group;\n" ::: "memory"); }

__device__ __forceinline__ void ldm4(uint32_t* r, uint32_t a) {
    asm volatile("ldmatrix.sync.aligned.m8n8.x4.shared.b16 {%0,%1,%2,%3}, [%4];"
                 : "=r"(r[0]), "=r"(r[1]), "=r"(r[2]), "=r"(r[3]) : "r"(a));
}
__device__ __forceinline__ void mma16816(float* c, const uint32_t* a, const uint32_t* b) {
    asm volatile(
        "mma.sync.aligned.m16n8k16.row.col.f32.f16.f16.f32 "
        "{%0,%1,%2,%3}, {%4,%5,%6,%7}, {%8,%9}, {%0,%1,%2,%3};"
        : "+f"(c[0]), "+f"(c[1]), "+f"(c[2]), "+f"(c[3])
        : "r"(a[0]), "r"(a[1]), "r"(a[2]), "r"(a[3]), "r"(b[0]), "r"(b[1]));
}
__device__ __forceinline__ void split2(float v, __half& h, __half& l) {
    h = __float2half(v);
    l = __float2half(v - __half2float(h));
}

// ---------------- mega prep kernel -------------------------------------------
#define PB_GATHER 0
#define PB_ENC    16384
#define PB_MAP    32768
#define PB_SPLIT  33024
#define PB_AWT    34560
#define PB_SST    34688
#define PB_BCONST 51072
#define PB_TOTAL  51264

__global__ void mega_prep(const int* __restrict__ target,
                          const float* __restrict__ emb,
                          const float* __restrict__ enc_attn,
                          const float* __restrict__ map_w,
                          const float* __restrict__ conv_w,
                          const float* __restrict__ affine_w,
                          const float* __restrict__ affine_b,
                          const float* __restrict__ src_seq) {
    const int bid = blockIdx.x;
    const int tid = threadIdx.x;

    if (bid < PB_ENC) {
        long gid = (long)(bid - PB_GATHER) * 256 + tid;
        int m = (int)(gid >> 7);
        int k = ((int)gid & 127) * 2;
        int b = m >> 10, t = m & 1023;
        int idx = target[t * NB + b];
        float2 v = *(const float2*)(emb + (long)idx * NE + k);
        __half2 hh; hh.x = __float2half(v.x); hh.y = __float2half(v.y);
        *(__half2*)(g_Gh + (long)m * NE + k) = hh;
    } else if (bid < PB_MAP) {
        long gid = (long)(bid - PB_ENC) * 256 + tid;
        float2 v = *(const float2*)(enc_attn + gid * 2);
        __half2 hh; hh.x = __float2half(v.x); hh.y = __float2half(v.y);
        *(__half2*)(g_EAb + gid * 2) = hh;
    } else if (bid < PB_SPLIT) {
        long gid = (long)(bid - PB_MAP) * 256 + tid;
        float2 v = *(const float2*)(map_w + gid * 2);
        __half2 hh; hh.x = __float2half(v.x); hh.y = __float2half(v.y);
        *(__half2*)(g_MWb + gid * 2) = hh;
    } else if (bid < PB_AWT) {
        long gid = (long)(bid - PB_SPLIT) * 256 + tid;
        float2 v = *(const float2*)(conv_w + gid * 2);
        __half h0, l0, h1, l1;
        split2(v.x, h0, l0); split2(v.y, h1, l1);
        __half2 hh; hh.x = h0; hh.y = h1;
        __half2 ll; ll.x = l0; ll.y = l1;
        *(__half2*)(g_CWh + gid * 2) = hh;
        *(__half2*)(g_CWl + gid * 2) = ll;
    } else if (bid < PB_SST) {
        __shared__ float tile[32][33];
        int lb = bid - PB_AWT;
        int i0 = (lb >> 3) * 32, e0 = (lb & 7) * 32;
        int tx = tid & 31, ty0 = tid >> 5;
        #pragma unroll
        for (int p = 0; p < 4; p++) {
            int ty = ty0 + p * 8;
            tile[ty][tx] = affine_w[(i0 + ty) * NE + e0 + tx];
        }
        __syncthreads();
        #pragma unroll
        for (int p = 0; p < 4; p++) {
            int ty = ty0 + p * 8;
            float v = tile[tx][ty];
            __half h, l; split2(v, h, l);
            long base = (long)(e0 + ty) * 1536 + i0 + tx;
            g_AWT[base] = h; g_AWT[base + 512] = l; g_AWT[base + 1024] = h;
        }
    } else if (bid < PB_BCONST) {
        __shared__ float tile[32][33];
        int lb = bid - PB_SST;
        int b = lb >> 9;
        int rem = lb & 511;
        int dy = rem >> 5, sx = rem & 31;
        int s0 = sx * 32, d0 = dy * 32;
        int tx = tid & 31, ty0 = tid >> 5;
        #pragma unroll
        for (int p = 0; p < 4; p++) {
            int ty = ty0 + p * 8;
            tile[ty][tx] = src_seq[((long)b * NS + s0 + ty) * NC2 + d0 + tx];
        }
        __syncthreads();
        #pragma unroll
        for (int p = 0; p < 4; p++) {
            int ty = ty0 + p * 8;
            g_SST[((long)b * NC2 + d0 + ty) * NS + s0 + tx] = __float2half(tile[tx][ty]);
        }
    } else {
        int wid = (bid - PB_BCONST) * 8 + (tid >> 5);
        int lane = tid & 31;
        int tap = wid / 512, o = wid % 512;
        const float* row = conv_w + (long)o * 1536 + tap * 512;
        float s = 0.f;
        for (int i = lane; i < 512; i += 32) s += row[i] * affine_b[i];
        #pragma unroll
        for (int off = 16; off > 0; off >>= 1) s += __shfl_xor_sync(~0u, s, off);
        if (lane == 0) g_BC[tap * 512 + o] = s;
    }
}

__global__ void biasrows_kernel(const float* __restrict__ conv_b) {
    int o = blockIdx.x * blockDim.x + threadIdx.x;
    if (o >= 512) return;
    float b = conv_b[o];
    float c0 = g_BC[o], c1 = g_BC[512 + o], c2 = g_BC[1024 + o];
    g_BR[o]        = b + c2;
    g_BR[512 + o]  = b + c1 + c2;
    g_BR[1024 + o] = b + c0 + c1 + c2;
}

// GLU: 2 rows per block, half2 loads
__global__ void glu_kernel() {
    int r  = threadIdx.x >> 7;
    int m  = blockIdx.x * 2 + r;
    int h2 = threadIdx.x & 127;
    const __half2* yrow = (const __half2*)(g_Yh + (long)m * NC2);
    __half2 a2 = yrow[h2];
    __half2 g2 = yrow[128 + h2];
    float a0 = fmaxf(__low2float(a2), 0.f), a1 = fmaxf(__high2float(a2), 0.f);
    float g0 = fmaxf(__low2float(g2), 0.f), g1 = fmaxf(__high2float(g2), 0.f);
    __shared__ float red[2][4];
    int lane = threadIdx.x & 31, wIn = (threadIdx.x >> 5) & 3;
    float v = fmaxf(g0, g1);
    #pragma unroll
    for (int o = 16; o > 0; o >>= 1) v = fmaxf(v, __shfl_xor_sync(~0u, v, o));
    if (lane == 0) red[r][wIn] = v;
    __syncthreads();
    float mx = fmaxf(fmaxf(red[r][0], red[r][1]), fmaxf(red[r][2], red[r][3]));
    float e0 = expf(g0 - mx), e1 = expf(g1 - mx);
    __syncthreads();
    v = e0 + e1;
    #pragma unroll
    for (int o = 16; o > 0; o >>= 1) v += __shfl_xor_sync(~0u, v, o);
    if (lane == 0) red[r][wIn] = v;
    __syncthreads();
    float sum = red[r][0] + red[r][1] + red[r][2] + red[r][3];
    float inv = 1.f / sum;
    __half2 d2; d2.x = __float2half(a0 * e0 * inv); d2.y = __float2half(a1 * e1 * inv);
    *(__half2*)(g_Dh + (long)m * NH + 2 * h2) = d2;
}

// softmax over fp16 scores -> fp16 probs
__global__ void softmax_rows_kernel() {
    int m = blockIdx.x;
    int h = threadIdx.x;
    const __half2* row = (const __half2*)(g_SCh + (long)m * NS);
    __half2 p0 = row[h];
    __half2 p1 = row[256 + h];
    float x0 = __low2float(p0), x1 = __high2float(p0);
    float x2 = __low2float(p1), x3 = __high2float(p1);
    __shared__ float red[8];
    float v = fmaxf(fmaxf(x0, x1), fmaxf(x2, x3));
    #pragma unroll
    for (int o = 16; o > 0; o >>= 1) v = fmaxf(v, __shfl_xor_sync(~0u, v, o));
    if ((h & 31) == 0) red[h >> 5] = v;
    __syncthreads();
    float mx = red[0];
    #pragma unroll
    for (int i = 1; i < 8; i++) mx = fmaxf(mx, red[i]);
    float e0 = expf(x0 - mx), e1 = expf(x1 - mx), e2 = expf(x2 - mx), e3 = expf(x3 - mx);
    __syncthreads();
    v = e0 + e1 + e2 + e3;
    #pragma unroll
    for (int o = 16; o > 0; o >>= 1) v += __shfl_xor_sync(~0u, v, o);
    if ((h & 31) == 0) red[h >> 5] = v;
    __syncthreads();
    float sum = 0.f;
    #pragma unroll
    for (int i = 0; i < 8; i++) sum += red[i];
    float inv = 1.f / sum;
    __half2* orow = (__half2*)(g_ATh + (long)m * NS);
    __half2 q0; q0.x = __float2half(e0 * inv); q0.y = __float2half(e1 * inv);
    __half2 q1; q1.x = __float2half(e2 * inv); q1.y = __float2half(e3 * inv);
    orow[h] = q0;
    orow[256 + h] = q1;
}

// ---------------- mma.sync fp16 GEMM: persistent tiles -----------------------
// R10 config: 256 thr, 8 warps (2x4), 64x32 warp tile, 128x128 block tile,
// BK=32, 4-stage cp.async, occupancy 2. Grid-stride loop over linear tile ids
// (x-major: consecutive tiles share the A panel).
// AMODE 0: A rows; aBatch!=0 -> A offset z*aBatch, rows by l.
// AMODE 2: fused conv on G. AMODE 3: concat Dh|ATh. BCAT: B concat map_w|SST.
// NSEG 3: A=[Ahi|Ahi|Alo], B 3-seg (FW precompute).
// EPI: 0 f32+bias1D, 3 fp16 write, 5 fp16+bias2D BR[min(l,2)].
#define GEMM_SMEM (4 * 16384)

template <int AMODE, int EPI, int NSEG, bool BCAT>
__global__ __launch_bounds__(256, 2)
void gemm_mma(const __half* __restrict__ AhiP, const __half* __restrict__ AloP, long aBatch,
              int KB, int lda, const __half* __restrict__ Bm, long bBatch,
              const __half* __restrict__ B2,
              const float* __restrict__ bias,
              float* __restrict__ C, int cLd,
              __half* __restrict__ Ohi, long oBatch,
              int Mb, int tilesX, int tilesY, int tilesZ) {
    extern __shared__ char smem[];
    const uint32_t sb = smem_u32(smem);
    const int tid = threadIdx.x;
    const int Kp = NSEG * KB;
    const int NK = Kp / 32;
    const int tilesXY = tilesX * tilesY;
    const int nTiles = tilesXY * tilesZ;

    const int w = tid >> 5, lid = tid & 31;
    const int wm = w >> 2, wn = w & 3;
    const int rl0 = wm * 64 + (lid & 15);
    const int aC = lid >> 4;
    const int nl0 = wn * 32 + ((lid >> 4) << 3) + (lid & 7);
    const int bC = (lid >> 3) & 1;
    const int ge = lid >> 2, t4 = lid & 3;

    for (int t = blockIdx.x; t < nTiles; t += gridDim.x) {
        const int z  = t / tilesXY;
        const int rr = t - z * tilesXY;
        const int l0 = (rr / tilesX) * 128;
        const int n0 = (rr - (rr / tilesX) * tilesX) * 128;
        const __half* Ahi = AhiP + (long)z * aBatch;
        const __half* Alo = (NSEG == 3) ? (AloP + (long)z * aBatch) : AloP;
        const __half* Bb = Bm + (long)z * bBatch;

        auto load_tile = [&](int kt, int st) {
            const int k0 = kt * 32;
            const uint32_t sA = sb + st * 16384;
            const uint32_t sB = sA + 8192;
            {
                const int seg = (NSEG == 3) ? (k0 / KB) : 0;
                const int rem0 = (NSEG == 3) ? (k0 - seg * KB) : k0;
                #pragma unroll
                for (int i = 0; i < 2; i++) {
                    int c = tid + i * 256;
                    int m = c >> 2, kc = c & 3;
                    int l = l0 + m;
                    long g; bool ok; const __half* Ab;
                    if (AMODE == 0) {
                        ok = (l < Mb);
                        long rowbase = aBatch ? (long)l : ((long)z * Mb + l);
                        g = rowbase * (long)lda + rem0 + kc * 8;
                        Ab = (NSEG == 3 && seg == 2) ? Alo : Ahi;
                    } else if (AMODE == 2) {
                        int tap = rem0 >> 8;
                        int e = (rem0 & 255) + kc * 8;
                        int tt = l - 2 + tap;
                        ok = (l < Mb) && (tt >= 0);
                        g = ((long)z * 1024 + tt) * 256 + e;
                        Ab = Ahi;
                    } else {
                        ok = (l < Mb);
                        if (k0 < 256) { g = ((long)z * Mb + l) * 256 + k0 + kc * 8; Ab = AhiP; }
                        else          { g = ((long)z * Mb + l) * 1024 + (k0 - 256) + kc * 8; Ab = AloP; }
                    }
                    cpasync16(sA + m * 64 + ((uint32_t)(kc ^ (m & 3)) << 4), Ab + (ok ? g : 0), ok);
                }
            }
            #pragma unroll
            for (int i = 0; i < 2; i++) {
                int c = tid + i * 256;
                int n = c >> 2, kc = c & 3;
                const __half* src; long g;
                if (BCAT) {
                    if (k0 < 256) { src = Bm; g = (long)(n0 + n) * 256 + k0 + kc * 8; }
                    else { src = B2; g = ((long)z * 512 + n0 + n) * 1024 + (k0 - 256) + kc * 8; }
                } else {
                    src = Bb; g = (long)(n0 + n) * Kp + k0 + kc * 8;
                }
                cpasync16(sB + n * 64 + ((uint32_t)(kc ^ (n & 3)) << 4), src + g, true);
            }
            cp_commit();
        };

        float acc[4][4][4];
        #pragma unroll
        for (int i = 0; i < 4; i++)
            #pragma unroll
            for (int j = 0; j < 4; j++)
                #pragma unroll
                for (int q = 0; q < 4; q++) acc[i][j][q] = 0.f;

        load_tile(0, 0); load_tile(1, 1); load_tile(2, 2);

        for (int kt = 0; kt < NK; kt++) {
            const int st = kt & 3;
            asm volatile("cp.async.wait_group 2;\n" ::: "memory");
            __syncthreads();
            if (kt + 3 < NK) load_tile(kt + 3, (kt + 3) & 3);
            else cp_commit();

            const uint32_t sA = sb + st * 16384;
            const uint32_t sB = sA + 8192;
            #pragma unroll
            for (int ks = 0; ks < 2; ks++) {
                uint32_t a[4][4];
                #pragma unroll
                for (int i = 0; i < 4; i++) {
                    int r = rl0 + i * 16;
                    ldm4(a[i], sA + r * 64 + ((uint32_t)((ks * 2 + aC) ^ (r & 3)) << 4));
                }
                uint32_t b[4][2];
                #pragma unroll
                for (int jj = 0; jj < 2; jj++) {
                    int n = nl0 + jj * 16;
                    uint32_t tt[4];
                    ldm4(tt, sB + n * 64 + ((uint32_t)((ks * 2 + bC) ^ (n & 3)) << 4));
                    b[jj * 2][0] = tt[0]; b[jj * 2][1] = tt[1];
                    b[jj * 2 + 1][0] = tt[2]; b[jj * 2 + 1][1] = tt[3];
                }
                #pragma unroll
                for (int i = 0; i < 4; i++)
                    #pragma unroll
                    for (int j = 0; j < 4; j++)
                        mma16816(acc[i][j], a[i], b[j]);
            }
        }

        // epilogue
        __half* Op = Ohi + (long)z * oBatch;
        #pragma unroll
        for (int i = 0; i < 4; i++) {
            #pragma unroll
            for (int h = 0; h < 2; h++) {
                int row = l0 + wm * 64 + i * 16 + ge + h * 8;
                if (row >= Mb) continue;
                long grow = (long)z * Mb + row;
                long orow = oBatch ? (long)row : grow;
                #pragma unroll
                for (int j = 0; j < 4; j++) {
                    int col = n0 + wn * 32 + j * 8 + 2 * t4;
                    float v0 = acc[i][j][h * 2 + 0];
                    float v1 = acc[i][j][h * 2 + 1];
                    if (EPI == 0) { v0 += bias[col]; v1 += bias[col + 1]; }
                    if (EPI == 5) {
                        int jb = (row < 2) ? row : 2;
                        v0 += bias[jb * 512 + col]; v1 += bias[jb * 512 + col + 1];
                    }
                    if (EPI == 3 || EPI == 5) {
                        __half2 hh; hh.x = __float2half(v0); hh.y = __float2half(v1);
                        *(__half2*)(Op + orow * (long)cLd + col) = hh;
                    } else {
                        float* cp = C + grow * (long)cLd + col;
                        float2 r; r.x = v0; r.y = v1;
                        *(float2*)cp = r;
                    }
                }
            }
        }
        __syncthreads();   // protect smem reuse by next tile's loads
    }
}

// ---------------- launcher ---------------------------------------------------
extern "C" void kernel_launch(void* const* d_in, const int* in_sizes, int n_in,
                              void* d_out, int out_size) {
    const int*   target   = (const int*)d_in[1];
    const float* enc_attn = (const float*)d_in[2];
    const float* src_seq  = (const float*)d_in[3];
    const float* emb      = (const float*)d_in[4];
    const float* affine_w = (const float*)d_in[5];
    const float* affine_b = (const float*)d_in[6];
    const float* conv_w   = (const float*)d_in[7];
    const float* conv_b   = (const float*)d_in[8];
    const float* map_w    = (const float*)d_in[9];
    const float* map_b    = (const float*)d_in[10];
    float* out = (float*)d_out;

    __half *Gh, *Yh, *Dh, *SCh, *ATh, *CWh, *CWl, *AWT, *FWB, *MWb, *EAb, *SST;
    float *BR;
    cudaGetSymbolAddress((void**)&Gh,  g_Gh);
    cudaGetSymbolAddress((void**)&Yh,  g_Yh);
    cudaGetSymbolAddress((void**)&Dh,  g_Dh);
    cudaGetSymbolAddress((void**)&SCh, g_SCh);
    cudaGetSymbolAddress((void**)&ATh, g_ATh);
    cudaGetSymbolAddress((void**)&CWh, g_CWh);   cudaGetSymbolAddress((void**)&CWl, g_CWl);
    cudaGetSymbolAddress((void**)&AWT, g_AWT);   cudaGetSymbolAddress((void**)&FWB, g_FWB);
    cudaGetSymbolAddress((void**)&MWb, g_MWb);   cudaGetSymbolAddress((void**)&EAb, g_EAb);
    cudaGetSymbolAddress((void**)&SST, g_SST);   cudaGetSymbolAddress((void**)&BR,  g_BR);

    cudaFuncSetAttribute(gemm_mma<0, 3, 3, false>, cudaFuncAttributeMaxDynamicSharedMemorySize, GEMM_SMEM);
    cudaFuncSetAttribute(gemm_mma<2, 5, 1, false>, cudaFuncAttributeMaxDynamicSharedMemorySize, GEMM_SMEM);
    cudaFuncSetAttribute(gemm_mma<0, 3, 1, false>, cudaFuncAttributeMaxDynamicSharedMemorySize, GEMM_SMEM);
    cudaFuncSetAttribute(gemm_mma<3, 0, 1, true>,  cudaFuncAttributeMaxDynamicSharedMemorySize, GEMM_SMEM);

    // 1. all conversions / weight prep in one launch
    mega_prep<<<PB_TOTAL, 256>>>(target, emb, enc_attn, map_w, conv_w,
                                 affine_w, affine_b, src_seq);
    // 2. bias rows
    biasrows_kernel<<<2, 256>>>(conv_b);
    // 3. fused weight (3-term, batched over taps): FW_tap = conv_w[.,tap,:] @ AWT
    gemm_mma<0, 3, 3, false><<<24, 256, GEMM_SMEM>>>(
        CWh, CWl, 512, 512, 1536, AWT, 0, nullptr,
        nullptr, nullptr, 768, FWB, 256, 512, 2, 4, 3);
    // 4. fused conv on G -> Yh fp16 (+bias rows)   (tiles 4x8x32 = 1024)
    gemm_mma<2, 5, 1, false><<<PERSIST, 256, GEMM_SMEM>>>(
        Gh, nullptr, 0, 768, 0, FWB, 0, nullptr, BR, nullptr, 512, Yh, 0, NL, 4, 8, NB);
    // 5. GLU -> Dh
    glu_kernel<<<NM2 / 2, 256>>>();
    // 6. scores -> SCh fp16 (tiles 8x8x32 = 2048)
    gemm_mma<0, 3, 1, false><<<PERSIST, 256, GEMM_SMEM>>>(
        Dh, nullptr, 0, 256, 256, EAb, (long)NS * NH, nullptr,
        nullptr, nullptr, NS, SCh, 0, NL, 8, 8, NB);
    // 7. softmax -> ATh fp16
    softmax_rows_kernel<<<NM2, 256>>>();
    // 8. combined: out = [Dh|ATh] @ [map_w|SST]^T + map_b   (tiles 4x8x32 = 1024)
    gemm_mma<3, 0, 1, true><<<PERSIST, 256, GEMM_SMEM>>>(
        Dh, ATh, 0, 1280, 0, MWb, 0, SST, map_b, out, 512, nullptr, 0, NL, 4, 8, NB);
}

// round 13
// speedup vs baseline: 1.1782x; 1.0052x over previous
#include <cuda_runtime.h>
#include <cuda_fp16.h>
#include <cstdint>

#define NB   32
#define NL   1023
#define NS   1024
#define NH   256
#define NC2  512
#define NE   256
#define NM1  32768
#define NM2  32736

// ---------------- scratch ----------------------------------------------------
__device__ __half g_Gh [NM1 * NE];
__device__ __half g_Yh [NM2 * NC2];
__device__ __half g_Dh [NM2 * NH];
__device__ __half g_SCh[(long)NM2 * NS];
__device__ __half g_ATh[(long)NM2 * NS];
__device__ __half g_CWh[NC2 * 1536], g_CWl[NC2 * 1536];
__device__ __half g_AWT[NE * 3 * NC2];
__device__ __half g_FWB[NC2 * 768];
__device__ __half g_MWb[NC2 * NH];
__device__ __half g_EAb[(long)NB * NS * NH];
__device__ __half g_SST[(long)NB * NC2 * NS];
__device__ float  g_BC [3 * NC2];

// ---------------- helpers ----------------------------------------------------
__device__ __forceinline__ uint32_t smem_u32(const void* p) {
    uint32_t a;
    asm("{ .reg .u64 t; cvta.to.shared.u64 t, %1; cvt.u32.u64 %0, t; }" : "=r"(a) : "l"(p));
    return a;
}
__device__ __forceinline__ void cpasync16(uint32_t s, const void* g, bool pred) {
    int sz = pred ? 16 : 0;
    asm volatile("cp.async.cg.shared.global [%0], [%1], 16, %2;\n" :: "r"(s), "l"(g), "r"(sz));
}
__device__ __forceinline__ void cp_commit() { asm volatile("cp.async.commit_group;\n" ::: "memory"); }

__device__ __forceinline__ void ldm4(uint32_t* r, uint32_t a) {
    asm volatile("ldmatrix.sync.aligned.m8n8.x4.shared.b16 {%0,%1,%2,%3}, [%4];"
                 : "=r"(r[0]), "=r"(r[1]), "=r"(r[2]), "=r"(r[3]) : "r"(a));
}
__device__ __forceinline__ void mma16816(float* c, const uint32_t* a, const uint32_t* b) {
    asm volatile(
        "mma.sync.aligned.m16n8k16.row.col.f32.f16.f16.f32 "
        "{%0,%1,%2,%3}, {%4,%5,%6,%7}, {%8,%9}, {%0,%1,%2,%3};"
        : "+f"(c[0]), "+f"(c[1]), "+f"(c[2]), "+f"(c[3])
        : "r"(a[0]), "r"(a[1]), "r"(a[2]), "r"(a[3]), "r"(b[0]), "r"(b[1]));
}
__device__ __forceinline__ void split2(float v, __half& h, __half& l) {
    h = __float2half(v);
    l = __float2half(v - __half2float(h));
}
__device__ __forceinline__ uint2 pack4h(float a, float b, float c, float d) {
    __half2 lo; lo.x = __float2half(a); lo.y = __float2half(b);
    __half2 hi; hi.x = __float2half(c); hi.y = __float2half(d);
    uint2 r; r.x = *(uint32_t*)&lo; r.y = *(uint32_t*)&hi;
    return r;
}

// ---------------- mega prep kernel (float4 / 4 elems per thread) -------------
#define PB_GATHER 0
#define PB_ENC    8192
#define PB_MAP    16384
#define PB_SPLIT  16512
#define PB_AWT    17280
#define PB_SST    17408
#define PB_BCONST 33792
#define PB_TOTAL  33984

__global__ void mega_prep(const int* __restrict__ target,
                          const float* __restrict__ emb,
                          const float* __restrict__ enc_attn,
                          const float* __restrict__ map_w,
                          const float* __restrict__ conv_w,
                          const float* __restrict__ affine_w,
                          const float* __restrict__ affine_b,
                          const float* __restrict__ src_seq) {
    const int bid = blockIdx.x;
    const int tid = threadIdx.x;

    if (bid < PB_ENC) {
        // gather + cast, one float4 per thread
        long q = (long)(bid - PB_GATHER) * 256 + tid;     // float4 id
        int m = (int)(q >> 6);                            // 64 float4 per row
        int k4 = (int)(q & 63);
        int b = m >> 10, t = m & 1023;
        int idx = target[t * NB + b];
        float4 v = *(const float4*)(emb + (long)idx * NE + k4 * 4);
        *(uint2*)(g_Gh + (long)m * NE + k4 * 4) = pack4h(v.x, v.y, v.z, v.w);
    } else if (bid < PB_MAP) {
        long q = (long)(bid - PB_ENC) * 256 + tid;
        float4 v = *(const float4*)(enc_attn + q * 4);
        *(uint2*)(g_EAb + q * 4) = pack4h(v.x, v.y, v.z, v.w);
    } else if (bid < PB_SPLIT) {
        long q = (long)(bid - PB_MAP) * 256 + tid;
        float4 v = *(const float4*)(map_w + q * 4);
        *(uint2*)(g_MWb + q * 4) = pack4h(v.x, v.y, v.z, v.w);
    } else if (bid < PB_AWT) {
        long q = (long)(bid - PB_SPLIT) * 256 + tid;
        float4 v = *(const float4*)(conv_w + q * 4);
        __half h0, l0, h1, l1, h2, l2, h3, l3;
        split2(v.x, h0, l0); split2(v.y, h1, l1);
        split2(v.z, h2, l2); split2(v.w, h3, l3);
        *(uint2*)(g_CWh + q * 4) = pack4h(__half2float(h0), __half2float(h1),
                                          __half2float(h2), __half2float(h3));
        *(uint2*)(g_CWl + q * 4) = pack4h(__half2float(l0), __half2float(l1),
                                          __half2float(l2), __half2float(l3));
    } else if (bid < PB_SST) {
        __shared__ float tile[32][33];
        int lb = bid - PB_AWT;
        int i0 = (lb >> 3) * 32, e0 = (lb & 7) * 32;
        int tx = tid & 31, ty0 = tid >> 5;
        #pragma unroll
        for (int p = 0; p < 4; p++) {
            int ty = ty0 + p * 8;
            tile[ty][tx] = affine_w[(i0 + ty) * NE + e0 + tx];
        }
        __syncthreads();
        #pragma unroll
        for (int p = 0; p < 4; p++) {
            int ty = ty0 + p * 8;
            float v = tile[tx][ty];
            __half h, l; split2(v, h, l);
            long base = (long)(e0 + ty) * 1536 + i0 + tx;
            g_AWT[base] = h; g_AWT[base + 512] = l; g_AWT[base + 1024] = h;
        }
    } else if (bid < PB_BCONST) {
        __shared__ float tile[32][33];
        int lb = bid - PB_SST;
        int b = lb >> 9;
        int rem = lb & 511;
        int dy = rem >> 5, sx = rem & 31;
        int s0 = sx * 32, d0 = dy * 32;
        int tx = tid & 31, ty0 = tid >> 5;
        #pragma unroll
        for (int p = 0; p < 4; p++) {
            int ty = ty0 + p * 8;
            tile[ty][tx] = src_seq[((long)b * NS + s0 + ty) * NC2 + d0 + tx];
        }
        __syncthreads();
        #pragma unroll
        for (int p = 0; p < 4; p++) {
            int ty = ty0 + p * 8;
            g_SST[((long)b * NC2 + d0 + ty) * NS + s0 + tx] = __float2half(tile[tx][ty]);
        }
    } else {
        int wid = (bid - PB_BCONST) * 8 + (tid >> 5);
        int lane = tid & 31;
        int tap = wid / 512, o = wid % 512;
        const float* row = conv_w + (long)o * 1536 + tap * 512;
        float s = 0.f;
        for (int i = lane; i < 512; i += 32) s += row[i] * affine_b[i];
        #pragma unroll
        for (int off = 16; off > 0; off >>= 1) s += __shfl_xor_sync(~0u, s, off);
        if (lane == 0) g_BC[tap * 512 + o] = s;
    }
}

// GLU: 2 rows per block, half2 loads
__global__ void glu_kernel() {
    int r  = threadIdx.x >> 7;
    int m  = blockIdx.x * 2 + r;
    int h2 = threadIdx.x & 127;
    const __half2* yrow = (const __half2*)(g_Yh + (long)m * NC2);
    __half2 a2 = yrow[h2];
    __half2 g2 = yrow[128 + h2];
    float a0 = fmaxf(__low2float(a2), 0.f), a1 = fmaxf(__high2float(a2), 0.f);
    float g0 = fmaxf(__low2float(g2), 0.f), g1 = fmaxf(__high2float(g2), 0.f);
    __shared__ float red[2][4];
    int lane = threadIdx.x & 31, wIn = (threadIdx.x >> 5) & 3;
    float v = fmaxf(g0, g1);
    #pragma unroll
    for (int o = 16; o > 0; o >>= 1) v = fmaxf(v, __shfl_xor_sync(~0u, v, o));
    if (lane == 0) red[r][wIn] = v;
    __syncthreads();
    float mx = fmaxf(fmaxf(red[r][0], red[r][1]), fmaxf(red[r][2], red[r][3]));
    float e0 = expf(g0 - mx), e1 = expf(g1 - mx);
    __syncthreads();
    v = e0 + e1;
    #pragma unroll
    for (int o = 16; o > 0; o >>= 1) v += __shfl_xor_sync(~0u, v, o);
    if (lane == 0) red[r][wIn] = v;
    __syncthreads();
    float sum = red[r][0] + red[r][1] + red[r][2] + red[r][3];
    float inv = 1.f / sum;
    __half2 d2; d2.x = __float2half(a0 * e0 * inv); d2.y = __float2half(a1 * e1 * inv);
    *(__half2*)(g_Dh + (long)m * NH + 2 * h2) = d2;
}

// softmax over fp16 scores -> fp16 probs
__global__ void softmax_rows_kernel() {
    int m = blockIdx.x;
    int h = threadIdx.x;
    const __half2* row = (const __half2*)(g_SCh + (long)m * NS);
    __half2 p0 = row[h];
    __half2 p1 = row[256 + h];
    float x0 = __low2float(p0), x1 = __high2float(p0);
    float x2 = __low2float(p1), x3 = __high2float(p1);
    __shared__ float red[8];
    float v = fmaxf(fmaxf(x0, x1), fmaxf(x2, x3));
    #pragma unroll
    for (int o = 16; o > 0; o >>= 1) v = fmaxf(v, __shfl_xor_sync(~0u, v, o));
    if ((h & 31) == 0) red[h >> 5] = v;
    __syncthreads();
    float mx = red[0];
    #pragma unroll
    for (int i = 1; i < 8; i++) mx = fmaxf(mx, red[i]);
    float e0 = expf(x0 - mx), e1 = expf(x1 - mx), e2 = expf(x2 - mx), e3 = expf(x3 - mx);
    __syncthreads();
    v = e0 + e1 + e2 + e3;
    #pragma unroll
    for (int o = 16; o > 0; o >>= 1) v += __shfl_xor_sync(~0u, v, o);
    if ((h & 31) == 0) red[h >> 5] = v;
    __syncthreads();
    float sum = 0.f;
    #pragma unroll
    for (int i = 0; i < 8; i++) sum += red[i];
    float inv = 1.f / sum;
    __half2* orow = (__half2*)(g_ATh + (long)m * NS);
    __half2 q0; q0.x = __float2half(e0 * inv); q0.y = __float2half(e1 * inv);
    __half2 q1; q1.x = __float2half(e2 * inv); q1.y = __float2half(e3 * inv);
    orow[h] = q0;
    orow[256 + h] = q1;
}

// ---------------- mma.sync fp16 GEMM (R10: 256 thr, 2x4 warps, 64x32 tile) ---
// Block 128x128, BK=32, 4-stage cp.async, occupancy 2.
// AMODE 0: A rows; aBatch!=0 -> A offset z*aBatch, rows by l.
// AMODE 2: fused conv on G. AMODE 3: concat Dh|ATh. BCAT: B concat map_w|SST.
// NSEG 3: A=[Ahi|Ahi|Alo], B 3-seg (FW precompute).
// EPI: 0 f32+bias1D, 3 fp16 write, 5 fp16 + conv bias computed from conv_b/g_BC.
#define GEMM_SMEM (4 * 16384)

template <int AMODE, int EPI, int NSEG, bool BCAT>
__global__ __launch_bounds__(256, 2)
void gemm_mma(const __half* __restrict__ Ahi, const __half* __restrict__ Alo, long aBatch,
              int KB, int lda, const __half* __restrict__ Bm, long bBatch,
              const __half* __restrict__ B2,
              const float* __restrict__ bias,
              float* __restrict__ C, int cLd,
              __half* __restrict__ Ohi, long oBatch,
              int Mb) {
    extern __shared__ char smem[];
    const uint32_t sb = smem_u32(smem);
    const int tid = threadIdx.x;
    const int z  = blockIdx.z;
    const int l0 = blockIdx.y * 128;
    const int n0 = blockIdx.x * 128;
    const int Kp = NSEG * KB;
    const int NK = Kp / 32;
    const __half* Bb = Bm + (long)z * bBatch;
    Ahi += (long)z * aBatch;
    if (NSEG == 3) Alo += (long)z * aBatch;

    auto load_tile = [&](int kt, int st) {
        const int k0 = kt * 32;
        const uint32_t sA = sb + st * 16384;
        const uint32_t sB = sA + 8192;
        {
            const int seg = (NSEG == 3) ? (k0 / KB) : 0;
            const int rem0 = (NSEG == 3) ? (k0 - seg * KB) : k0;
            #pragma unroll
            for (int i = 0; i < 2; i++) {
                int c = tid + i * 256;
                int m = c >> 2, kc = c & 3;
                int l = l0 + m;
                long g; bool ok; const __half* Ab;
                if (AMODE == 0) {
                    ok = (l < Mb);
                    long rowbase = aBatch ? (long)l : ((long)z * Mb + l);
                    g = rowbase * (long)lda + rem0 + kc * 8;
                    Ab = (NSEG == 3 && seg == 2) ? Alo : Ahi;
                } else if (AMODE == 2) {
                    int tap = rem0 >> 8;
                    int e = (rem0 & 255) + kc * 8;
                    int t = l - 2 + tap;
                    ok = (l < Mb) && (t >= 0);
                    g = ((long)z * 1024 + t) * 256 + e;
                    Ab = Ahi;
                } else {
                    ok = (l < Mb);
                    if (k0 < 256) { g = ((long)z * Mb + l) * 256 + k0 + kc * 8; Ab = Ahi; }
                    else          { g = ((long)z * Mb + l) * 1024 + (k0 - 256) + kc * 8; Ab = Alo; }
                }
                cpasync16(sA + m * 64 + ((uint32_t)(kc ^ (m & 3)) << 4), Ab + (ok ? g : 0), ok);
            }
        }
        #pragma unroll
        for (int i = 0; i < 2; i++) {
            int c = tid + i * 256;
            int n = c >> 2, kc = c & 3;
            const __half* src; long g;
            if (BCAT) {
                if (k0 < 256) { src = Bm; g = (long)(n0 + n) * 256 + k0 + kc * 8; }
                else { src = B2; g = ((long)z * 512 + n0 + n) * 1024 + (k0 - 256) + kc * 8; }
            } else {
                src = Bb; g = (long)(n0 + n) * Kp + k0 + kc * 8;
            }
            cpasync16(sB + n * 64 + ((uint32_t)(kc ^ (n & 3)) << 4), src + g, true);
        }
        cp_commit();
    };

    float acc[4][4][4];
    #pragma unroll
    for (int i = 0; i < 4; i++)
        #pragma unroll
        for (int j = 0; j < 4; j++)
            #pragma unroll
            for (int q = 0; q < 4; q++) acc[i][j][q] = 0.f;

    const int w = tid >> 5, lid = tid & 31;
    const int wm = w >> 2, wn = w & 3;
    const int rl = wm * 64 + (lid & 15);
    const int aC = lid >> 4;
    const int nl = wn * 32 + ((lid >> 4) << 3) + (lid & 7);
    const int bC = (lid >> 3) & 1;

    load_tile(0, 0); load_tile(1, 1); load_tile(2, 2);

    for (int kt = 0; kt < NK; kt++) {
        const int st = kt & 3;
        asm volatile("cp.async.wait_group 2;\n" ::: "memory");
        __syncthreads();
        if (kt + 3 < NK) load_tile(kt + 3, (kt + 3) & 3);
        else cp_commit();

        const uint32_t sA = sb + st * 16384;
        const uint32_t sB = sA + 8192;
        #pragma unroll
        for (int ks = 0; ks < 2; ks++) {
            uint32_t a[4][4];
            #pragma unroll
            for (int i = 0; i < 4; i++) {
                int r = rl + i * 16;
                ldm4(a[i], sA + r * 64 + ((uint32_t)((ks * 2 + aC) ^ (r & 3)) << 4));
            }
            uint32_t b[4][2];
            #pragma unroll
            for (int jj = 0; jj < 2; jj++) {
                int n = nl + jj * 16;
                uint32_t t[4];
                ldm4(t, sB + n * 64 + ((uint32_t)((ks * 2 + bC) ^ (n & 3)) << 4));
                b[jj * 2][0] = t[0]; b[jj * 2][1] = t[1];
                b[jj * 2 + 1][0] = t[2]; b[jj * 2 + 1][1] = t[3];
            }
            #pragma unroll
            for (int i = 0; i < 4; i++)
                #pragma unroll
                for (int j = 0; j < 4; j++)
                    mma16816(acc[i][j], a[i], b[j]);
        }
    }

    // ---------------- epilogue ----------------
    const int g  = lid >> 2, t4 = lid & 3;
    __half* Op = Ohi + (long)z * oBatch;
    #pragma unroll
    for (int i = 0; i < 4; i++) {
        #pragma unroll
        for (int h = 0; h < 2; h++) {
            int row = l0 + wm * 64 + i * 16 + g + h * 8;
            if (row >= Mb) continue;
            long grow = (long)z * Mb + row;
            long orow = oBatch ? (long)row : grow;
            #pragma unroll
            for (int j = 0; j < 4; j++) {
                int col = n0 + wn * 32 + j * 8 + 2 * t4;
                float v0 = acc[i][j][h * 2 + 0];
                float v1 = acc[i][j][h * 2 + 1];
                if (EPI == 0) { v0 += bias[col]; v1 += bias[col + 1]; }
                if (EPI == 5) {
                    float b0 = bias[col]     + g_BC[1024 + col];
                    float b1 = bias[col + 1] + g_BC[1024 + col + 1];
                    if (row >= 1) { b0 += g_BC[512 + col]; b1 += g_BC[512 + col + 1]; }
                    if (row >= 2) { b0 += g_BC[col];       b1 += g_BC[col + 1]; }
                    v0 += b0; v1 += b1;
                }
                if (EPI == 3 || EPI == 5) {
                    __half2 hh; hh.x = __float2half(v0); hh.y = __float2half(v1);
                    *(__half2*)(Op + orow * (long)cLd + col) = hh;
                } else {
                    float* cp = C + grow * (long)cLd + col;
                    float2 r; r.x = v0; r.y = v1;
                    *(float2*)cp = r;
                }
            }
        }
    }
}

// ---------------- launcher ---------------------------------------------------
extern "C" void kernel_launch(void* const* d_in, const int* in_sizes, int n_in,
                              void* d_out, int out_size) {
    const int*   target   = (const int*)d_in[1];
    const float* enc_attn = (const float*)d_in[2];
    const float* src_seq  = (const float*)d_in[3];
    const float* emb      = (const float*)d_in[4];
    const float* affine_w = (const float*)d_in[5];
    const float* affine_b = (const float*)d_in[6];
    const float* conv_w   = (const float*)d_in[7];
    const float* conv_b   = (const float*)d_in[8];
    const float* map_w    = (const float*)d_in[9];
    const float* map_b    = (const float*)d_in[10];
    float* out = (float*)d_out;

    __half *Gh, *Yh, *Dh, *SCh, *ATh, *CWh, *CWl, *AWT, *FWB, *MWb, *EAb, *SST;
    cudaGetSymbolAddress((void**)&Gh,  g_Gh);
    cudaGetSymbolAddress((void**)&Yh,  g_Yh);
    cudaGetSymbolAddress((void**)&Dh,  g_Dh);
    cudaGetSymbolAddress((void**)&SCh, g_SCh);
    cudaGetSymbolAddress((void**)&ATh, g_ATh);
    cudaGetSymbolAddress((void**)&CWh, g_CWh);   cudaGetSymbolAddress((void**)&CWl, g_CWl);
    cudaGetSymbolAddress((void**)&AWT, g_AWT);   cudaGetSymbolAddress((void**)&FWB, g_FWB);
    cudaGetSymbolAddress((void**)&MWb, g_MWb);   cudaGetSymbolAddress((void**)&EAb, g_EAb);
    cudaGetSymbolAddress((void**)&SST, g_SST);

    cudaFuncSetAttribute(gemm_mma<0, 3, 3, false>, cudaFuncAttributeMaxDynamicSharedMemorySize, GEMM_SMEM);
    cudaFuncSetAttribute(gemm_mma<2, 5, 1, false>, cudaFuncAttributeMaxDynamicSharedMemorySize, GEMM_SMEM);
    cudaFuncSetAttribute(gemm_mma<0, 3, 1, false>, cudaFuncAttributeMaxDynamicSharedMemorySize, GEMM_SMEM);
    cudaFuncSetAttribute(gemm_mma<3, 0, 1, true>,  cudaFuncAttributeMaxDynamicSharedMemorySize, GEMM_SMEM);

    // 1. all conversions / weight prep in one launch
    mega_prep<<<PB_TOTAL, 256>>>(target, emb, enc_attn, map_w, conv_w,
                                 affine_w, affine_b, src_seq);
    // 2. fused weight (3-term, batched over taps): FW_tap = conv_w[.,tap,:] @ AWT
    gemm_mma<0, 3, 3, false><<<dim3(2, 4, 3), 256, GEMM_SMEM>>>(
        CWh, CWl, 512, 512, 1536, AWT, 0, nullptr,
        nullptr, nullptr, 768, FWB, 256, 512);
    // 3. fused conv on G -> Yh fp16 (+conv bias folded in epilogue)
    gemm_mma<2, 5, 1, false><<<dim3(4, 8, NB), 256, GEMM_SMEM>>>(
        Gh, nullptr, 0, 768, 0, FWB, 0, nullptr, conv_b, nullptr, 512, Yh, 0, NL);
    // 4. GLU -> Dh
    glu_kernel<<<NM2 / 2, 256>>>();
    // 5. scores -> SCh fp16 (batched)  (N=1024, K=256)
    gemm_mma<0, 3, 1, false><<<dim3(8, 8, NB), 256, GEMM_SMEM>>>(
        Dh, nullptr, 0, 256, 256, EAb, (long)NS * NH, nullptr,
        nullptr, nullptr, NS, SCh, 0, NL);
    // 6. softmax -> ATh fp16
    softmax_rows_kernel<<<NM2, 256>>>();
    // 7. combined: out = [Dh|ATh] @ [map_w|SST]^T + map_b   (N=512, K=1280)
    gemm_mma<3, 0, 1, true><<<dim3(4, 8, NB), 256, GEMM_SMEM>>>(
        Dh, ATh, 0, 1280, 0, MWb, 0, SST, map_b, out, 512, nullptr, 0, NL);
}

// round 14
// speedup vs baseline: 1.1966x; 1.0156x over previous
#include <cuda_runtime.h>
#include <cuda_fp16.h>
#include <cstdint>

#define NB   32
#define NL   1023
#define NS   1024
#define NH   256
#define NC2  512
#define NE   256
#define NM1  32768
#define NM2  32736

// ---------------- scratch ----------------------------------------------------
__device__ __half g_Gh [NM1 * NE];
__device__ __half g_Yh [NM2 * NC2];
__device__ __half g_Dh [NM2 * NH];
__device__ __half g_SCh[(long)NM2 * NS];
__device__ __half g_ATh[(long)NM2 * NS];
__device__ __half g_CWh[NC2 * 1536], g_CWl[NC2 * 1536];
__device__ __half g_AWT[NE * 3 * NC2];
__device__ __half g_FWB[NC2 * 768];
__device__ __half g_MWb[NC2 * NH];
__device__ __half g_EAb[(long)NB * NS * NH];
__device__ __half g_SST[(long)NB * NC2 * NS];
__device__ float  g_BC [3 * NC2];

// ---------------- helpers ----------------------------------------------------
__device__ __forceinline__ uint32_t smem_u32(const void* p) {
    uint32_t a;
    asm("{ .reg .u64 t; cvta.to.shared.u64 t, %1; cvt.u32.u64 %0, t; }" : "=r"(a) : "l"(p));
    return a;
}
__device__ __forceinline__ void cpasync16(uint32_t s, const void* g, bool pred) {
    int sz = pred ? 16 : 0;
    asm volatile("cp.async.cg.shared.global [%0], [%1], 16, %2;\n" :: "r"(s), "l"(g), "r"(sz));
}
__device__ __forceinline__ void cp_commit() { asm volatile("cp.async.commit_group;\n" ::: "memory"); }

__device__ __forceinline__ void ldm4(uint32_t* r, uint32_t a) {
    asm volatile("ldmatrix.sync.aligned.m8n8.x4.shared.b16 {%0,%1,%2,%3}, [%4];"
                 : "=r"(r[0]), "=r"(r[1]), "=r"(r[2]), "=r"(r[3]) : "r"(a));
}
__device__ __forceinline__ void mma16816(float* c, const uint32_t* a, const uint32_t* b) {
    asm volatile(
        "mma.sync.aligned.m16n8k16.row.col.f32.f16.f16.f32 "
        "{%0,%1,%2,%3}, {%4,%5,%6,%7}, {%8,%9}, {%0,%1,%2,%3};"
        : "+f"(c[0]), "+f"(c[1]), "+f"(c[2]), "+f"(c[3])
        : "r"(a[0]), "r"(a[1]), "r"(a[2]), "r"(a[3]), "r"(b[0]), "r"(b[1]));
}
__device__ __forceinline__ void split2(float v, __half& h, __half& l) {
    h = __float2half(v);
    l = __float2half(v - __half2float(h));
}
__device__ __forceinline__ uint2 pack4h(float a, float b, float c, float d) {
    __half2 lo; lo.x = __float2half(a); lo.y = __float2half(b);
    __half2 hi; hi.x = __float2half(c); hi.y = __float2half(d);
    uint2 r; r.x = *(uint32_t*)&lo; r.y = *(uint32_t*)&hi;
    return r;
}

// ---------------- mega prep kernel (float4 / 4 elems per thread) -------------
#define PB_GATHER 0
#define PB_ENC    8192
#define PB_MAP    16384
#define PB_SPLIT  16512
#define PB_AWT    17280
#define PB_SST    17408
#define PB_BCONST 33792
#define PB_TOTAL  33984

__global__ void mega_prep(const int* __restrict__ target,
                          const float* __restrict__ emb,
                          const float* __restrict__ enc_attn,
                          const float* __restrict__ map_w,
                          const float* __restrict__ conv_w,
                          const float* __restrict__ affine_w,
                          const float* __restrict__ affine_b,
                          const float* __restrict__ src_seq) {
    const int bid = blockIdx.x;
    const int tid = threadIdx.x;

    if (bid < PB_ENC) {
        long q = (long)(bid - PB_GATHER) * 256 + tid;
        int m = (int)(q >> 6);
        int k4 = (int)(q & 63);
        int b = m >> 10, t = m & 1023;
        int idx = target[t * NB + b];
        float4 v = *(const float4*)(emb + (long)idx * NE + k4 * 4);
        *(uint2*)(g_Gh + (long)m * NE + k4 * 4) = pack4h(v.x, v.y, v.z, v.w);
    } else if (bid < PB_MAP) {
        long q = (long)(bid - PB_ENC) * 256 + tid;
        float4 v = *(const float4*)(enc_attn + q * 4);
        *(uint2*)(g_EAb + q * 4) = pack4h(v.x, v.y, v.z, v.w);
    } else if (bid < PB_SPLIT) {
        long q = (long)(bid - PB_MAP) * 256 + tid;
        float4 v = *(const float4*)(map_w + q * 4);
        *(uint2*)(g_MWb + q * 4) = pack4h(v.x, v.y, v.z, v.w);
    } else if (bid < PB_AWT) {
        long q = (long)(bid - PB_SPLIT) * 256 + tid;
        float4 v = *(const float4*)(conv_w + q * 4);
        __half h0, l0, h1, l1, h2, l2, h3, l3;
        split2(v.x, h0, l0); split2(v.y, h1, l1);
        split2(v.z, h2, l2); split2(v.w, h3, l3);
        *(uint2*)(g_CWh + q * 4) = pack4h(__half2float(h0), __half2float(h1),
                                          __half2float(h2), __half2float(h3));
        *(uint2*)(g_CWl + q * 4) = pack4h(__half2float(l0), __half2float(l1),
                                          __half2float(l2), __half2float(l3));
    } else if (bid < PB_SST) {
        __shared__ float tile[32][33];
        int lb = bid - PB_AWT;
        int i0 = (lb >> 3) * 32, e0 = (lb & 7) * 32;
        int tx = tid & 31, ty0 = tid >> 5;
        #pragma unroll
        for (int p = 0; p < 4; p++) {
            int ty = ty0 + p * 8;
            tile[ty][tx] = affine_w[(i0 + ty) * NE + e0 + tx];
        }
        __syncthreads();
        #pragma unroll
        for (int p = 0; p < 4; p++) {
            int ty = ty0 + p * 8;
            float v = tile[tx][ty];
            __half h, l; split2(v, h, l);
            long base = (long)(e0 + ty) * 1536 + i0 + tx;
            g_AWT[base] = h; g_AWT[base + 512] = l; g_AWT[base + 1024] = h;
        }
    } else if (bid < PB_BCONST) {
        __shared__ float tile[32][33];
        int lb = bid - PB_SST;
        int b = lb >> 9;
        int rem = lb & 511;
        int dy = rem >> 5, sx = rem & 31;
        int s0 = sx * 32, d0 = dy * 32;
        int tx = tid & 31, ty0 = tid >> 5;
        #pragma unroll
        for (int p = 0; p < 4; p++) {
            int ty = ty0 + p * 8;
            tile[ty][tx] = src_seq[((long)b * NS + s0 + ty) * NC2 + d0 + tx];
        }
        __syncthreads();
        #pragma unroll
        for (int p = 0; p < 4; p++) {
            int ty = ty0 + p * 8;
            g_SST[((long)b * NC2 + d0 + ty) * NS + s0 + tx] = __float2half(tile[tx][ty]);
        }
    } else {
        int wid = (bid - PB_BCONST) * 8 + (tid >> 5);
        int lane = tid & 31;
        int tap = wid / 512, o = wid % 512;
        const float* row = conv_w + (long)o * 1536 + tap * 512;
        float s = 0.f;
        for (int i = lane; i < 512; i += 32) s += row[i] * affine_b[i];
        #pragma unroll
        for (int off = 16; off > 0; off >>= 1) s += __shfl_xor_sync(~0u, s, off);
        if (lane == 0) g_BC[tap * 512 + o] = s;
    }
}

// GLU: 2 rows per block, half2 loads, fast exp
__global__ void glu_kernel() {
    int r  = threadIdx.x >> 7;
    int m  = blockIdx.x * 2 + r;
    int h2 = threadIdx.x & 127;
    const __half2* yrow = (const __half2*)(g_Yh + (long)m * NC2);
    __half2 a2 = yrow[h2];
    __half2 g2 = yrow[128 + h2];
    float a0 = fmaxf(__low2float(a2), 0.f), a1 = fmaxf(__high2float(a2), 0.f);
    float g0 = fmaxf(__low2float(g2), 0.f), g1 = fmaxf(__high2float(g2), 0.f);
    __shared__ float red[2][4];
    int lane = threadIdx.x & 31, wIn = (threadIdx.x >> 5) & 3;
    float v = fmaxf(g0, g1);
    #pragma unroll
    for (int o = 16; o > 0; o >>= 1) v = fmaxf(v, __shfl_xor_sync(~0u, v, o));
    if (lane == 0) red[r][wIn] = v;
    __syncthreads();
    float mx = fmaxf(fmaxf(red[r][0], red[r][1]), fmaxf(red[r][2], red[r][3]));
    float e0 = __expf(g0 - mx), e1 = __expf(g1 - mx);
    __syncthreads();
    v = e0 + e1;
    #pragma unroll
    for (int o = 16; o > 0; o >>= 1) v += __shfl_xor_sync(~0u, v, o);
    if (lane == 0) red[r][wIn] = v;
    __syncthreads();
    float sum = red[r][0] + red[r][1] + red[r][2] + red[r][3];
    float inv = 1.f / sum;
    __half2 d2; d2.x = __float2half(a0 * e0 * inv); d2.y = __float2half(a1 * e1 * inv);
    *(__half2*)(g_Dh + (long)m * NH + 2 * h2) = d2;
}

// softmax over fp16 scores -> fp16 probs, fast exp
__global__ void softmax_rows_kernel() {
    int m = blockIdx.x;
    int h = threadIdx.x;
    const __half2* row = (const __half2*)(g_SCh + (long)m * NS);
    __half2 p0 = row[h];
    __half2 p1 = row[256 + h];
    float x0 = __low2float(p0), x1 = __high2float(p0);
    float x2 = __low2float(p1), x3 = __high2float(p1);
    __shared__ float red[8];
    float v = fmaxf(fmaxf(x0, x1), fmaxf(x2, x3));
    #pragma unroll
    for (int o = 16; o > 0; o >>= 1) v = fmaxf(v, __shfl_xor_sync(~0u, v, o));
    if ((h & 31) == 0) red[h >> 5] = v;
    __syncthreads();
    float mx = red[0];
    #pragma unroll
    for (int i = 1; i < 8; i++) mx = fmaxf(mx, red[i]);
    float e0 = __expf(x0 - mx), e1 = __expf(x1 - mx),
          e2 = __expf(x2 - mx), e3 = __expf(x3 - mx);
    __syncthreads();
    v = e0 + e1 + e2 + e3;
    #pragma unroll
    for (int o = 16; o > 0; o >>= 1) v += __shfl_xor_sync(~0u, v, o);
    if ((h & 31) == 0) red[h >> 5] = v;
    __syncthreads();
    float sum = 0.f;
    #pragma unroll
    for (int i = 0; i < 8; i++) sum += red[i];
    float inv = 1.f / sum;
    __half2* orow = (__half2*)(g_ATh + (long)m * NS);
    __half2 q0; q0.x = __float2half(e0 * inv); q0.y = __float2half(e1 * inv);
    __half2 q1; q1.x = __float2half(e2 * inv); q1.y = __float2half(e3 * inv);
    orow[h] = q0;
    orow[256 + h] = q1;
}

// ---------------- mma.sync fp16 GEMM (R10: 256 thr, 2x4 warps, 64x32 tile) ---
#define GEMM_SMEM (4 * 16384)

template <int AMODE, int EPI, int NSEG, bool BCAT>
__global__ __launch_bounds__(256, 2)
void gemm_mma(const __half* __restrict__ Ahi, const __half* __restrict__ Alo, long aBatch,
              int KB, int lda, const __half* __restrict__ Bm, long bBatch,
              const __half* __restrict__ B2,
              const float* __restrict__ bias,
              float* __restrict__ C, int cLd,
              __half* __restrict__ Ohi, long oBatch,
              int Mb) {
    extern __shared__ char smem[];
    const uint32_t sb = smem_u32(smem);
    const int tid = threadIdx.x;
    const int z  = blockIdx.z;
    const int l0 = blockIdx.y * 128;
    const int n0 = blockIdx.x * 128;
    const int Kp = NSEG * KB;
    const int NK = Kp / 32;
    const __half* Bb = Bm + (long)z * bBatch;
    Ahi += (long)z * aBatch;
    if (NSEG == 3) Alo += (long)z * aBatch;

    auto load_tile = [&](int kt, int st) {
        const int k0 = kt * 32;
        const uint32_t sA = sb + st * 16384;
        const uint32_t sB = sA + 8192;
        {
            const int seg = (NSEG == 3) ? (k0 / KB) : 0;
            const int rem0 = (NSEG == 3) ? (k0 - seg * KB) : k0;
            #pragma unroll
            for (int i = 0; i < 2; i++) {
                int c = tid + i * 256;
                int m = c >> 2, kc = c & 3;
                int l = l0 + m;
                long g; bool ok; const __half* Ab;
                if (AMODE == 0) {
                    ok = (l < Mb);
                    long rowbase = aBatch ? (long)l : ((long)z * Mb + l);
                    g = rowbase * (long)lda + rem0 + kc * 8;
                    Ab = (NSEG == 3 && seg == 2) ? Alo : Ahi;
                } else if (AMODE == 2) {
                    int tap = rem0 >> 8;
                    int e = (rem0 & 255) + kc * 8;
                    int t = l - 2 + tap;
                    ok = (l < Mb) && (t >= 0);
                    g = ((long)z * 1024 + t) * 256 + e;
                    Ab = Ahi;
                } else {
                    ok = (l < Mb);
                    if (k0 < 256) { g = ((long)z * Mb + l) * 256 + k0 + kc * 8; Ab = Ahi; }
                    else          { g = ((long)z * Mb + l) * 1024 + (k0 - 256) + kc * 8; Ab = Alo; }
                }
                cpasync16(sA + m * 64 + ((uint32_t)(kc ^ (m & 3)) << 4), Ab + (ok ? g : 0), ok);
            }
        }
        #pragma unroll
        for (int i = 0; i < 2; i++) {
            int c = tid + i * 256;
            int n = c >> 2, kc = c & 3;
            const __half* src; long g;
            if (BCAT) {
                if (k0 < 256) { src = Bm; g = (long)(n0 + n) * 256 + k0 + kc * 8; }
                else { src = B2; g = ((long)z * 512 + n0 + n) * 1024 + (k0 - 256) + kc * 8; }
            } else {
                src = Bb; g = (long)(n0 + n) * Kp + k0 + kc * 8;
            }
            cpasync16(sB + n * 64 + ((uint32_t)(kc ^ (n & 3)) << 4), src + g, true);
        }
        cp_commit();
    };

    float acc[4][4][4];
    #pragma unroll
    for (int i = 0; i < 4; i++)
        #pragma unroll
        for (int j = 0; j < 4; j++)
            #pragma unroll
            for (int q = 0; q < 4; q++) acc[i][j][q] = 0.f;

    const int w = tid >> 5, lid = tid & 31;
    const int wm = w >> 2, wn = w & 3;
    const int rl = wm * 64 + (lid & 15);
    const int aC = lid >> 4;
    const int nl = wn * 32 + ((lid >> 4) << 3) + (lid & 7);
    const int bC = (lid >> 3) & 1;

    load_tile(0, 0); load_tile(1, 1); load_tile(2, 2);

    for (int kt = 0; kt < NK; kt++) {
        const int st = kt & 3;
        asm volatile("cp.async.wait_group 2;\n" ::: "memory");
        __syncthreads();
        if (kt + 3 < NK) load_tile(kt + 3, (kt + 3) & 3);
        else cp_commit();

        const uint32_t sA = sb + st * 16384;
        const uint32_t sB = sA + 8192;
        #pragma unroll
        for (int ks = 0; ks < 2; ks++) {
            uint32_t a[4][4];
            #pragma unroll
            for (int i = 0; i < 4; i++) {
                int r = rl + i * 16;
                ldm4(a[i], sA + r * 64 + ((uint32_t)((ks * 2 + aC) ^ (r & 3)) << 4));
            }
            uint32_t b[4][2];
            #pragma unroll
            for (int jj = 0; jj < 2; jj++) {
                int n = nl + jj * 16;
                uint32_t t[4];
                ldm4(t, sB + n * 64 + ((uint32_t)((ks * 2 + bC) ^ (n & 3)) << 4));
                b[jj * 2][0] = t[0]; b[jj * 2][1] = t[1];
                b[jj * 2 + 1][0] = t[2]; b[jj * 2 + 1][1] = t[3];
            }
            #pragma unroll
            for (int i = 0; i < 4; i++)
                #pragma unroll
                for (int j = 0; j < 4; j++)
                    mma16816(acc[i][j], a[i], b[j]);
        }
    }

    // ---------------- epilogue ----------------
    const int g  = lid >> 2, t4 = lid & 3;
    __half* Op = Ohi + (long)z * oBatch;
    #pragma unroll
    for (int i = 0; i < 4; i++) {
        #pragma unroll
        for (int h = 0; h < 2; h++) {
            int row = l0 + wm * 64 + i * 16 + g + h * 8;
            if (row >= Mb) continue;
            long grow = (long)z * Mb + row;
            long orow = oBatch ? (long)row : grow;
            #pragma unroll
            for (int j = 0; j < 4; j++) {
                int col = n0 + wn * 32 + j * 8 + 2 * t4;
                float v0 = acc[i][j][h * 2 + 0];
                float v1 = acc[i][j][h * 2 + 1];
                if (EPI == 0) { v0 += bias[col]; v1 += bias[col + 1]; }
                if (EPI == 5) {
                    float b0 = bias[col]     + g_BC[1024 + col];
                    float b1 = bias[col + 1] + g_BC[1024 + col + 1];
                    if (row >= 1) { b0 += g_BC[512 + col]; b1 += g_BC[512 + col + 1]; }
                    if (row >= 2) { b0 += g_BC[col];       b1 += g_BC[col + 1]; }
                    v0 += b0; v1 += b1;
                }
                if (EPI == 3 || EPI == 5) {
                    __half2 hh; hh.x = __float2half(v0); hh.y = __float2half(v1);
                    *(__half2*)(Op + orow * (long)cLd + col) = hh;
                } else {
                    float* cp = C + grow * (long)cLd + col;
                    float2 r; r.x = v0; r.y = v1;
                    *(float2*)cp = r;
                }
            }
        }
    }
}

// ---------------- launcher ---------------------------------------------------
extern "C" void kernel_launch(void* const* d_in, const int* in_sizes, int n_in,
                              void* d_out, int out_size) {
    const int*   target   = (const int*)d_in[1];
    const float* enc_attn = (const float*)d_in[2];
    const float* src_seq  = (const float*)d_in[3];
    const float* emb      = (const float*)d_in[4];
    const float* affine_w = (const float*)d_in[5];
    const float* affine_b = (const float*)d_in[6];
    const float* conv_w   = (const float*)d_in[7];
    const float* conv_b   = (const float*)d_in[8];
    const float* map_w    = (const float*)d_in[9];
    const float* map_b    = (const float*)d_in[10];
    float* out = (float*)d_out;

    __half *Gh, *Yh, *Dh, *SCh, *ATh, *CWh, *CWl, *AWT, *FWB, *MWb, *EAb, *SST;
    cudaGetSymbolAddress((void**)&Gh,  g_Gh);
    cudaGetSymbolAddress((void**)&Yh,  g_Yh);
    cudaGetSymbolAddress((void**)&Dh,  g_Dh);
    cudaGetSymbolAddress((void**)&SCh, g_SCh);
    cudaGetSymbolAddress((void**)&ATh, g_ATh);
    cudaGetSymbolAddress((void**)&CWh, g_CWh);   cudaGetSymbolAddress((void**)&CWl, g_CWl);
    cudaGetSymbolAddress((void**)&AWT, g_AWT);   cudaGetSymbolAddress((void**)&FWB, g_FWB);
    cudaGetSymbolAddress((void**)&MWb, g_MWb);   cudaGetSymbolAddress((void**)&EAb, g_EAb);
    cudaGetSymbolAddress((void**)&SST, g_SST);

    cudaFuncSetAttribute(gemm_mma<0, 3, 3, false>, cudaFuncAttributeMaxDynamicSharedMemorySize, GEMM_SMEM);
    cudaFuncSetAttribute(gemm_mma<2, 5, 1, false>, cudaFuncAttributeMaxDynamicSharedMemorySize, GEMM_SMEM);
    cudaFuncSetAttribute(gemm_mma<0, 3, 1, false>, cudaFuncAttributeMaxDynamicSharedMemorySize, GEMM_SMEM);
    cudaFuncSetAttribute(gemm_mma<3, 0, 1, true>,  cudaFuncAttributeMaxDynamicSharedMemorySize, GEMM_SMEM);

    // 1. all conversions / weight prep in one launch
    mega_prep<<<PB_TOTAL, 256>>>(target, emb, enc_attn, map_w, conv_w,
                                 affine_w, affine_b, src_seq);
    // 2. fused weight (3-term, batched over taps): FW_tap = conv_w[.,tap,:] @ AWT
    gemm_mma<0, 3, 3, false><<<dim3(2, 4, 3), 256, GEMM_SMEM>>>(
        CWh, CWl, 512, 512, 1536, AWT, 0, nullptr,
        nullptr, nullptr, 768, FWB, 256, 512);
    // 3. fused conv on G -> Yh fp16 (+conv bias folded in epilogue)
    gemm_mma<2, 5, 1, false><<<dim3(4, 8, NB), 256, GEMM_SMEM>>>(
        Gh, nullptr, 0, 768, 0, FWB, 0, nullptr, conv_b, nullptr, 512, Yh, 0, NL);
    // 4. GLU -> Dh
    glu_kernel<<<NM2 / 2, 256>>>();
    // 5. scores -> SCh fp16 (batched)  (N=1024, K=256)
    gemm_mma<0, 3, 1, false><<<dim3(8, 8, NB), 256, GEMM_SMEM>>>(
        Dh, nullptr, 0, 256, 256, EAb, (long)NS * NH, nullptr,
        nullptr, nullptr, NS, SCh, 0, NL);
    // 6. softmax -> ATh fp16
    softmax_rows_kernel<<<NM2, 256>>>();
    // 7. combined: out = [Dh|ATh] @ [map_w|SST]^T + map_b   (N=512, K=1280)
    gemm_mma<3, 0, 1, true><<<dim3(4, 8, NB), 256, GEMM_SMEM>>>(
        Dh, ATh, 0, 1280, 0, MWb, 0, SST, map_b, out, 512, nullptr, 0, NL);
}

// round 15
// speedup vs baseline: 1.2104x; 1.0116x over previous
#include <cuda_runtime.h>
#include <cuda_fp16.h>
#include <cstdint>

#define NB   32
#define NL   1023
#define NS   1024
#define NH   256
#define NC2  512
#define NE   256
#define NM1  32768
#define NM2  32736

// ---------------- scratch ----------------------------------------------------
__device__ __half g_Gh [NM1 * NE];
__device__ __half g_Yh [NM2 * NC2];
__device__ __half g_Dh [NM2 * NH];
__device__ __half g_SCh[(long)NM2 * NS];
__device__ __half g_ATh[(long)NM2 * NS];
__device__ __half g_CWh[NC2 * 1536], g_CWl[NC2 * 1536];
__device__ __half g_AWT[NE * 3 * NC2];
__device__ __half g_FWB[NC2 * 768];
__device__ __half g_MWb[NC2 * NH];
__device__ __half g_EAb[(long)NB * NS * NH];
__device__ __half g_SST[(long)NB * NC2 * NS];
__device__ float  g_BC [3 * NC2];

// ---------------- helpers ----------------------------------------------------
__device__ __forceinline__ uint32_t smem_u32(const void* p) {
    uint32_t a;
    asm("{ .reg .u64 t; cvta.to.shared.u64 t, %1; cvt.u32.u64 %0, t; }" : "=r"(a) : "l"(p));
    return a;
}
__device__ __forceinline__ void cpasync16(uint32_t s, const void* g, bool pred) {
    int sz = pred ? 16 : 0;
    asm volatile("cp.async.cg.shared.global [%0], [%1], 16, %2;\n" :: "r"(s), "l"(g), "r"(sz));
}
__device__ __forceinline__ void cp_commit() { asm volatile("cp.async.commit_group;\n" ::: "memory"); }

__device__ __forceinline__ void ldm4(uint32_t* r, uint32_t a) {
    asm volatile("ldmatrix.sync.aligned.m8n8.x4.shared.b16 {%0,%1,%2,%3}, [%4];"
                 : "=r"(r[0]), "=r"(r[1]), "=r"(r[2]), "=r"(r[3]) : "r"(a));
}
__device__ __forceinline__ void mma16816(float* c, const uint32_t* a, const uint32_t* b) {
    asm volatile(
        "mma.sync.aligned.m16n8k16.row.col.f32.f16.f16.f32 "
        "{%0,%1,%2,%3}, {%4,%5,%6,%7}, {%8,%9}, {%0,%1,%2,%3};"
        : "+f"(c[0]), "+f"(c[1]), "+f"(c[2]), "+f"(c[3])
        : "r"(a[0]), "r"(a[1]), "r"(a[2]), "r"(a[3]), "r"(b[0]), "r"(b[1]));
}
__device__ __forceinline__ void split2(float v, __half& h, __half& l) {
    h = __float2half(v);
    l = __float2half(v - __half2float(h));
}
__device__ __forceinline__ uint2 pack4h(float a, float b, float c, float d) {
    __half2 lo; lo.x = __float2half(a); lo.y = __float2half(b);
    __half2 hi; hi.x = __float2half(c); hi.y = __float2half(d);
    uint2 r; r.x = *(uint32_t*)&lo; r.y = *(uint32_t*)&hi;
    return r;
}

// ---------------- mega prep kernel (float4 / 4 elems per thread) -------------
#define PB_GATHER 0
#define PB_ENC    8192
#define PB_MAP    16384
#define PB_SPLIT  16512
#define PB_AWT    17280
#define PB_SST    17408
#define PB_BCONST 33792
#define PB_TOTAL  33984

__global__ void mega_prep(const int* __restrict__ target,
                          const float* __restrict__ emb,
                          const float* __restrict__ enc_attn,
                          const float* __restrict__ map_w,
                          const float* __restrict__ conv_w,
                          const float* __restrict__ affine_w,
                          const float* __restrict__ affine_b,
                          const float* __restrict__ src_seq) {
    const int bid = blockIdx.x;
    const int tid = threadIdx.x;

    if (bid < PB_ENC) {
        long q = (long)(bid - PB_GATHER) * 256 + tid;
        int m = (int)(q >> 6);
        int k4 = (int)(q & 63);
        int b = m >> 10, t = m & 1023;
        int idx = target[t * NB + b];
        float4 v = *(const float4*)(emb + (long)idx * NE + k4 * 4);
        *(uint2*)(g_Gh + (long)m * NE + k4 * 4) = pack4h(v.x, v.y, v.z, v.w);
    } else if (bid < PB_MAP) {
        long q = (long)(bid - PB_ENC) * 256 + tid;
        float4 v = *(const float4*)(enc_attn + q * 4);
        *(uint2*)(g_EAb + q * 4) = pack4h(v.x, v.y, v.z, v.w);
    } else if (bid < PB_SPLIT) {
        long q = (long)(bid - PB_MAP) * 256 + tid;
        float4 v = *(const float4*)(map_w + q * 4);
        *(uint2*)(g_MWb + q * 4) = pack4h(v.x, v.y, v.z, v.w);
    } else if (bid < PB_AWT) {
        long q = (long)(bid - PB_SPLIT) * 256 + tid;
        float4 v = *(const float4*)(conv_w + q * 4);
        __half h0, l0, h1, l1, h2, l2, h3, l3;
        split2(v.x, h0, l0); split2(v.y, h1, l1);
        split2(v.z, h2, l2); split2(v.w, h3, l3);
        *(uint2*)(g_CWh + q * 4) = pack4h(__half2float(h0), __half2float(h1),
                                          __half2float(h2), __half2float(h3));
        *(uint2*)(g_CWl + q * 4) = pack4h(__half2float(l0), __half2float(l1),
                                          __half2float(l2), __half2float(l3));
    } else if (bid < PB_SST) {
        __shared__ float tile[32][33];
        int lb = bid - PB_AWT;
        int i0 = (lb >> 3) * 32, e0 = (lb & 7) * 32;
        int tx = tid & 31, ty0 = tid >> 5;
        #pragma unroll
        for (int p = 0; p < 4; p++) {
            int ty = ty0 + p * 8;
            tile[ty][tx] = affine_w[(i0 + ty) * NE + e0 + tx];
        }
        __syncthreads();
        #pragma unroll
        for (int p = 0; p < 4; p++) {
            int ty = ty0 + p * 8;
            float v = tile[tx][ty];
            __half h, l; split2(v, h, l);
            long base = (long)(e0 + ty) * 1536 + i0 + tx;
            g_AWT[base] = h; g_AWT[base + 512] = l; g_AWT[base + 1024] = h;
        }
    } else if (bid < PB_BCONST) {
        __shared__ float tile[32][33];
        int lb = bid - PB_SST;
        int b = lb >> 9;
        int rem = lb & 511;
        int dy = rem >> 5, sx = rem & 31;
        int s0 = sx * 32, d0 = dy * 32;
        int tx = tid & 31, ty0 = tid >> 5;
        #pragma unroll
        for (int p = 0; p < 4; p++) {
            int ty = ty0 + p * 8;
            tile[ty][tx] = src_seq[((long)b * NS + s0 + ty) * NC2 + d0 + tx];
        }
        __syncthreads();
        #pragma unroll
        for (int p = 0; p < 4; p++) {
            int ty = ty0 + p * 8;
            g_SST[((long)b * NC2 + d0 + ty) * NS + s0 + tx] = __float2half(tile[tx][ty]);
        }
    } else {
        int wid = (bid - PB_BCONST) * 8 + (tid >> 5);
        int lane = tid & 31;
        int tap = wid / 512, o = wid % 512;
        const float* row = conv_w + (long)o * 1536 + tap * 512;
        float s = 0.f;
        for (int i = lane; i < 512; i += 32) s += row[i] * affine_b[i];
        #pragma unroll
        for (int off = 16; off > 0; off >>= 1) s += __shfl_xor_sync(~0u, s, off);
        if (lane == 0) g_BC[tap * 512 + o] = s;
    }
}

// GLU: warp per row, zero smem / zero block barriers
__global__ void glu_kernel() {
    int wid = threadIdx.x >> 5;                // 8 warps/block
    int m   = blockIdx.x * 8 + wid;
    int lane = threadIdx.x & 31;
    const uint4* yrow = (const uint4*)(g_Yh + (long)m * NC2);
    uint4 av = yrow[lane];                     // a: halves [lane*8, lane*8+8)
    uint4 gv = yrow[32 + lane];                // gate
    const __half2* ah = (const __half2*)&av;
    const __half2* gh = (const __half2*)&gv;
    float a[8], g[8];
    #pragma unroll
    for (int i = 0; i < 4; i++) {
        a[2*i]   = fmaxf(__low2float(ah[i]), 0.f);
        a[2*i+1] = fmaxf(__high2float(ah[i]), 0.f);
        g[2*i]   = fmaxf(__low2float(gh[i]), 0.f);
        g[2*i+1] = fmaxf(__high2float(gh[i]), 0.f);
    }
    float mx = g[0];
    #pragma unroll
    for (int i = 1; i < 8; i++) mx = fmaxf(mx, g[i]);
    #pragma unroll
    for (int o = 16; o > 0; o >>= 1) mx = fmaxf(mx, __shfl_xor_sync(~0u, mx, o));
    float e[8], sum = 0.f;
    #pragma unroll
    for (int i = 0; i < 8; i++) { e[i] = __expf(g[i] - mx); sum += e[i]; }
    #pragma unroll
    for (int o = 16; o > 0; o >>= 1) sum += __shfl_xor_sync(~0u, sum, o);
    float inv = 1.f / sum;
    uint4 dv;
    __half2* dh = (__half2*)&dv;
    #pragma unroll
    for (int i = 0; i < 4; i++) {
        dh[i].x = __float2half(a[2*i]   * e[2*i]   * inv);
        dh[i].y = __float2half(a[2*i+1] * e[2*i+1] * inv);
    }
    *(uint4*)(g_Dh + (long)m * NH + lane * 8) = dv;
}

// softmax over fp16 scores -> fp16 probs, fast exp
__global__ void softmax_rows_kernel() {
    int m = blockIdx.x;
    int h = threadIdx.x;
    const __half2* row = (const __half2*)(g_SCh + (long)m * NS);
    __half2 p0 = row[h];
    __half2 p1 = row[256 + h];
    float x0 = __low2float(p0), x1 = __high2float(p0);
    float x2 = __low2float(p1), x3 = __high2float(p1);
    __shared__ float red[8];
    float v = fmaxf(fmaxf(x0, x1), fmaxf(x2, x3));
    #pragma unroll
    for (int o = 16; o > 0; o >>= 1) v = fmaxf(v, __shfl_xor_sync(~0u, v, o));
    if ((h & 31) == 0) red[h >> 5] = v;
    __syncthreads();
    float mx = red[0];
    #pragma unroll
    for (int i = 1; i < 8; i++) mx = fmaxf(mx, red[i]);
    float e0 = __expf(x0 - mx), e1 = __expf(x1 - mx),
          e2 = __expf(x2 - mx), e3 = __expf(x3 - mx);
    __syncthreads();
    v = e0 + e1 + e2 + e3;
    #pragma unroll
    for (int o = 16; o > 0; o >>= 1) v += __shfl_xor_sync(~0u, v, o);
    if ((h & 31) == 0) red[h >> 5] = v;
    __syncthreads();
    float sum = 0.f;
    #pragma unroll
    for (int i = 0; i < 8; i++) sum += red[i];
    float inv = 1.f / sum;
    __half2* orow = (__half2*)(g_ATh + (long)m * NS);
    __half2 q0; q0.x = __float2half(e0 * inv); q0.y = __float2half(e1 * inv);
    __half2 q1; q1.x = __float2half(e2 * inv); q1.y = __float2half(e3 * inv);
    orow[h] = q0;
    orow[256 + h] = q1;
}

// ---------------- mma.sync fp16 GEMM (R10: 256 thr, 2x4 warps, 64x32 tile) ---
#define GEMM_SMEM (4 * 16384)

template <int AMODE, int EPI, int NSEG, bool BCAT>
__global__ __launch_bounds__(256, 2)
void gemm_mma(const __half* __restrict__ Ahi, const __half* __restrict__ Alo, long aBatch,
              int KB, int lda, const __half* __restrict__ Bm, long bBatch,
              const __half* __restrict__ B2,
              const float* __restrict__ bias,
              float* __restrict__ C, int cLd,
              __half* __restrict__ Ohi, long oBatch,
              int Mb) {
    extern __shared__ char smem[];
    const uint32_t sb = smem_u32(smem);
    const int tid = threadIdx.x;
    const int z  = blockIdx.z;
    const int l0 = blockIdx.y * 128;
    const int n0 = blockIdx.x * 128;
    const int Kp = NSEG * KB;
    const int NK = Kp / 32;
    const __half* Bb = Bm + (long)z * bBatch;
    Ahi += (long)z * aBatch;
    if (NSEG == 3) Alo += (long)z * aBatch;

    auto load_tile = [&](int kt, int st) {
        const int k0 = kt * 32;
        const uint32_t sA = sb + st * 16384;
        const uint32_t sB = sA + 8192;
        {
            const int seg = (NSEG == 3) ? (k0 / KB) : 0;
            const int rem0 = (NSEG == 3) ? (k0 - seg * KB) : k0;
            #pragma unroll
            for (int i = 0; i < 2; i++) {
                int c = tid + i * 256;
                int m = c >> 2, kc = c & 3;
                int l = l0 + m;
                long g; bool ok; const __half* Ab;
                if (AMODE == 0) {
                    ok = (l < Mb);
                    long rowbase = aBatch ? (long)l : ((long)z * Mb + l);
                    g = rowbase * (long)lda + rem0 + kc * 8;
                    Ab = (NSEG == 3 && seg == 2) ? Alo : Ahi;
                } else if (AMODE == 2) {
                    int tap = rem0 >> 8;
                    int e = (rem0 & 255) + kc * 8;
                    int t = l - 2 + tap;
                    ok = (l < Mb) && (t >= 0);
                    g = ((long)z * 1024 + t) * 256 + e;
                    Ab = Ahi;
                } else {
                    ok = (l < Mb);
                    if (k0 < 256) { g = ((long)z * Mb + l) * 256 + k0 + kc * 8; Ab = Ahi; }
                    else          { g = ((long)z * Mb + l) * 1024 + (k0 - 256) + kc * 8; Ab = Alo; }
                }
                cpasync16(sA + m * 64 + ((uint32_t)(kc ^ (m & 3)) << 4), Ab + (ok ? g : 0), ok);
            }
        }
        #pragma unroll
        for (int i = 0; i < 2; i++) {
            int c = tid + i * 256;
            int n = c >> 2, kc = c & 3;
            const __half* src; long g;
            if (BCAT) {
                if (k0 < 256) { src = Bm; g = (long)(n0 + n) * 256 + k0 + kc * 8; }
                else { src = B2; g = ((long)z * 512 + n0 + n) * 1024 + (k0 - 256) + kc * 8; }
            } else {
                src = Bb; g = (long)(n0 + n) * Kp + k0 + kc * 8;
            }
            cpasync16(sB + n * 64 + ((uint32_t)(kc ^ (n & 3)) << 4), src + g, true);
        }
        cp_commit();
    };

    float acc[4][4][4];
    #pragma unroll
    for (int i = 0; i < 4; i++)
        #pragma unroll
        for (int j = 0; j < 4; j++)
            #pragma unroll
            for (int q = 0; q < 4; q++) acc[i][j][q] = 0.f;

    const int w = tid >> 5, lid = tid & 31;
    const int wm = w >> 2, wn = w & 3;
    const int rl = wm * 64 + (lid & 15);
    const int aC = lid >> 4;
    const int nl = wn * 32 + ((lid >> 4) << 3) + (lid & 7);
    const int bC = (lid >> 3) & 1;

    load_tile(0, 0); load_tile(1, 1); load_tile(2, 2);

    for (int kt = 0; kt < NK; kt++) {
        const int st = kt & 3;
        asm volatile("cp.async.wait_group 2;\n" ::: "memory");
        __syncthreads();
        if (kt + 3 < NK) load_tile(kt + 3, (kt + 3) & 3);
        else cp_commit();

        const uint32_t sA = sb + st * 16384;
        const uint32_t sB = sA + 8192;
        #pragma unroll
        for (int ks = 0; ks < 2; ks++) {
            uint32_t a[4][4];
            #pragma unroll
            for (int i = 0; i < 4; i++) {
                int r = rl + i * 16;
                ldm4(a[i], sA + r * 64 + ((uint32_t)((ks * 2 + aC) ^ (r & 3)) << 4));
            }
            uint32_t b[4][2];
            #pragma unroll
            for (int jj = 0; jj < 2; jj++) {
                int n = nl + jj * 16;
                uint32_t t[4];
                ldm4(t, sB + n * 64 + ((uint32_t)((ks * 2 + bC) ^ (n & 3)) << 4));
                b[jj * 2][0] = t[0]; b[jj * 2][1] = t[1];
                b[jj * 2 + 1][0] = t[2]; b[jj * 2 + 1][1] = t[3];
            }
            #pragma unroll
            for (int i = 0; i < 4; i++)
                #pragma unroll
                for (int j = 0; j < 4; j++)
                    mma16816(acc[i][j], a[i], b[j]);
        }
    }

    // ---------------- epilogue ----------------
    const int g  = lid >> 2, t4 = lid & 3;
    __half* Op = Ohi + (long)z * oBatch;
    #pragma unroll
    for (int i = 0; i < 4; i++) {
        #pragma unroll
        for (int h = 0; h < 2; h++) {
            int row = l0 + wm * 64 + i * 16 + g + h * 8;
            if (row >= Mb) continue;
            long grow = (long)z * Mb + row;
            long orow = oBatch ? (long)row : grow;
            #pragma unroll
            for (int j = 0; j < 4; j++) {
                int col = n0 + wn * 32 + j * 8 + 2 * t4;
                float v0 = acc[i][j][h * 2 + 0];
                float v1 = acc[i][j][h * 2 + 1];
                if (EPI == 0) { v0 += bias[col]; v1 += bias[col + 1]; }
                if (EPI == 5) {
                    float b0 = bias[col]     + g_BC[1024 + col];
                    float b1 = bias[col + 1] + g_BC[1024 + col + 1];
                    if (row >= 1) { b0 += g_BC[512 + col]; b1 += g_BC[512 + col + 1]; }
                    if (row >= 2) { b0 += g_BC[col];       b1 += g_BC[col + 1]; }
                    v0 += b0; v1 += b1;
                }
                if (EPI == 3 || EPI == 5) {
                    __half2 hh; hh.x = __float2half(v0); hh.y = __float2half(v1);
                    *(__half2*)(Op + orow * (long)cLd + col) = hh;
                } else {
                    float* cp = C + grow * (long)cLd + col;
                    float2 r; r.x = v0; r.y = v1;
                    *(float2*)cp = r;
                }
            }
        }
    }
}

// ---------------- launcher ---------------------------------------------------
extern "C" void kernel_launch(void* const* d_in, const int* in_sizes, int n_in,
                              void* d_out, int out_size) {
    const int*   target   = (const int*)d_in[1];
    const float* enc_attn = (const float*)d_in[2];
    const float* src_seq  = (const float*)d_in[3];
    const float* emb      = (const float*)d_in[4];
    const float* affine_w = (const float*)d_in[5];
    const float* affine_b = (const float*)d_in[6];
    const float* conv_w   = (const float*)d_in[7];
    const float* conv_b   = (const float*)d_in[8];
    const float* map_w    = (const float*)d_in[9];
    const float* map_b    = (const float*)d_in[10];
    float* out = (float*)d_out;

    __half *Gh, *Yh, *Dh, *SCh, *ATh, *CWh, *CWl, *AWT, *FWB, *MWb, *EAb, *SST;
    cudaGetSymbolAddress((void**)&Gh,  g_Gh);
    cudaGetSymbolAddress((void**)&Yh,  g_Yh);
    cudaGetSymbolAddress((void**)&Dh,  g_Dh);
    cudaGetSymbolAddress((void**)&SCh, g_SCh);
    cudaGetSymbolAddress((void**)&ATh, g_ATh);
    cudaGetSymbolAddress((void**)&CWh, g_CWh);   cudaGetSymbolAddress((void**)&CWl, g_CWl);
    cudaGetSymbolAddress((void**)&AWT, g_AWT);   cudaGetSymbolAddress((void**)&FWB, g_FWB);
    cudaGetSymbolAddress((void**)&MWb, g_MWb);   cudaGetSymbolAddress((void**)&EAb, g_EAb);
    cudaGetSymbolAddress((void**)&SST, g_SST);

    cudaFuncSetAttribute(gemm_mma<0, 3, 3, false>, cudaFuncAttributeMaxDynamicSharedMemorySize, GEMM_SMEM);
    cudaFuncSetAttribute(gemm_mma<2, 5, 1, false>, cudaFuncAttributeMaxDynamicSharedMemorySize, GEMM_SMEM);
    cudaFuncSetAttribute(gemm_mma<0, 3, 1, false>, cudaFuncAttributeMaxDynamicSharedMemorySize, GEMM_SMEM);
    cudaFuncSetAttribute(gemm_mma<3, 0, 1, true>,  cudaFuncAttributeMaxDynamicSharedMemorySize, GEMM_SMEM);

    // 1. all conversions / weight prep in one launch
    mega_prep<<<PB_TOTAL, 256>>>(target, emb, enc_attn, map_w, conv_w,
                                 affine_w, affine_b, src_seq);
    // 2. fused weight (3-term, batched over taps): FW_tap = conv_w[.,tap,:] @ AWT
    gemm_mma<0, 3, 3, false><<<dim3(2, 4, 3), 256, GEMM_SMEM>>>(
        CWh, CWl, 512, 512, 1536, AWT, 0, nullptr,
        nullptr, nullptr, 768, FWB, 256, 512);
    // 3. fused conv on G -> Yh fp16 (+conv bias folded in epilogue)
    gemm_mma<2, 5, 1, false><<<dim3(4, 8, NB), 256, GEMM_SMEM>>>(
        Gh, nullptr, 0, 768, 0, FWB, 0, nullptr, conv_b, nullptr, 512, Yh, 0, NL);
    // 4. GLU -> Dh (warp per row)
    glu_kernel<<<NM2 / 8, 256>>>();
    // 5. scores -> SCh fp16 (batched)  (N=1024, K=256)
    gemm_mma<0, 3, 1, false><<<dim3(8, 8, NB), 256, GEMM_SMEM>>>(
        Dh, nullptr, 0, 256, 256, EAb, (long)NS * NH, nullptr,
        nullptr, nullptr, NS, SCh, 0, NL);
    // 6. softmax -> ATh fp16
    softmax_rows_kernel<<<NM2, 256>>>();
    // 7. combined: out = [Dh|ATh] @ [map_w|SST]^T + map_b   (N=512, K=1280)
    gemm_mma<3, 0, 1, true><<<dim3(4, 8, NB), 256, GEMM_SMEM>>>(
        Dh, ATh, 0, 1280, 0, MWb, 0, SST, map_b, out, 512, nullptr, 0, NL);
}

// round 16
// speedup vs baseline: 1.2706x; 1.0497x over previous
#include <cuda_runtime.h>
#include <cuda_fp16.h>
#include <cstdint>

#define NB   32
#define NL   1023
#define NS   1024
#define NH   256
#define NC2  512
#define NE   256
#define NM1  32768
#define NM2  32736

// ---------------- scratch ----------------------------------------------------
__device__ __half g_Gh [NM1 * NE];
__device__ __half g_Yh [NM2 * NC2];
__device__ __half g_Dh [NM2 * NH];
__device__ __half g_SCh[(long)NM2 * NS];
__device__ __half g_ATh[(long)NM2 * NS];
__device__ __half g_CWh[NC2 * 1536], g_CWl[NC2 * 1536];
__device__ __half g_AWT[NE * 3 * NC2];
__device__ __half g_FWB[NC2 * 768];
__device__ __half g_MWb[NC2 * NH];
__device__ __half g_EAb[(long)NB * NS * NH];
__device__ __half g_SST[(long)NB * NC2 * NS];
__device__ float  g_BC [3 * NC2];

// ---------------- helpers ----------------------------------------------------
__device__ __forceinline__ uint32_t smem_u32(const void* p) {
    uint32_t a;
    asm("{ .reg .u64 t; cvta.to.shared.u64 t, %1; cvt.u32.u64 %0, t; }" : "=r"(a) : "l"(p));
    return a;
}
__device__ __forceinline__ void cpasync16(uint32_t s, const void* g, bool pred) {
    int sz = pred ? 16 : 0;
    asm volatile("cp.async.cg.shared.global [%0], [%1], 16, %2;\n" :: "r"(s), "l"(g), "r"(sz));
}
__device__ __forceinline__ void cp_commit() { asm volatile("cp.async.commit_group;\n" ::: "memory"); }

__device__ __forceinline__ void ldm4(uint32_t* r, uint32_t a) {
    asm volatile("ldmatrix.sync.aligned.m8n8.x4.shared.b16 {%0,%1,%2,%3}, [%4];"
                 : "=r"(r[0]), "=r"(r[1]), "=r"(r[2]), "=r"(r[3]) : "r"(a));
}
__device__ __forceinline__ void mma16816(float* c, const uint32_t* a, const uint32_t* b) {
    asm volatile(
        "mma.sync.aligned.m16n8k16.row.col.f32.f16.f16.f32 "
        "{%0,%1,%2,%3}, {%4,%5,%6,%7}, {%8,%9}, {%0,%1,%2,%3};"
        : "+f"(c[0]), "+f"(c[1]), "+f"(c[2]), "+f"(c[3])
        : "r"(a[0]), "r"(a[1]), "r"(a[2]), "r"(a[3]), "r"(b[0]), "r"(b[1]));
}
__device__ __forceinline__ void split2(float v, __half& h, __half& l) {
    h = __float2half(v);
    l = __float2half(v - __half2float(h));
}
__device__ __forceinline__ uint2 pack4h(float a, float b, float c, float d) {
    __half2 lo; lo.x = __float2half(a); lo.y = __float2half(b);
    __half2 hi; hi.x = __float2half(c); hi.y = __float2half(d);
    uint2 r; r.x = *(uint32_t*)&lo; r.y = *(uint32_t*)&hi;
    return r;
}

// ---------------- mega prep kernel (float4 / 4 elems per thread) -------------
#define PB_GATHER 0
#define PB_ENC    8192
#define PB_MAP    16384
#define PB_SPLIT  16512
#define PB_AWT    17280
#define PB_SST    17408
#define PB_BCONST 33792
#define PB_TOTAL  33984

__global__ void mega_prep(const int* __restrict__ target,
                          const float* __restrict__ emb,
                          const float* __restrict__ enc_attn,
                          const float* __restrict__ map_w,
                          const float* __restrict__ conv_w,
                          const float* __restrict__ affine_w,
                          const float* __restrict__ affine_b,
                          const float* __restrict__ src_seq) {
    const int bid = blockIdx.x;
    const int tid = threadIdx.x;

    if (bid < PB_ENC) {
        long q = (long)(bid - PB_GATHER) * 256 + tid;
        int m = (int)(q >> 6);
        int k4 = (int)(q & 63);
        int b = m >> 10, t = m & 1023;
        int idx = target[t * NB + b];
        float4 v = *(const float4*)(emb + (long)idx * NE + k4 * 4);
        *(uint2*)(g_Gh + (long)m * NE + k4 * 4) = pack4h(v.x, v.y, v.z, v.w);
    } else if (bid < PB_MAP) {
        long q = (long)(bid - PB_ENC) * 256 + tid;
        float4 v = *(const float4*)(enc_attn + q * 4);
        *(uint2*)(g_EAb + q * 4) = pack4h(v.x, v.y, v.z, v.w);
    } else if (bid < PB_SPLIT) {
        long q = (long)(bid - PB_MAP) * 256 + tid;
        float4 v = *(const float4*)(map_w + q * 4);
        *(uint2*)(g_MWb + q * 4) = pack4h(v.x, v.y, v.z, v.w);
    } else if (bid < PB_AWT) {
        long q = (long)(bid - PB_SPLIT) * 256 + tid;
        float4 v = *(const float4*)(conv_w + q * 4);
        __half h0, l0, h1, l1, h2, l2, h3, l3;
        split2(v.x, h0, l0); split2(v.y, h1, l1);
        split2(v.z, h2, l2); split2(v.w, h3, l3);
        *(uint2*)(g_CWh + q * 4) = pack4h(__half2float(h0), __half2float(h1),
                                          __half2float(h2), __half2float(h3));
        *(uint2*)(g_CWl + q * 4) = pack4h(__half2float(l0), __half2float(l1),
                                          __half2float(l2), __half2float(l3));
    } else if (bid < PB_SST) {
        __shared__ float tile[32][33];
        int lb = bid - PB_AWT;
        int i0 = (lb >> 3) * 32, e0 = (lb & 7) * 32;
        int tx = tid & 31, ty0 = tid >> 5;
        #pragma unroll
        for (int p = 0; p < 4; p++) {
            int ty = ty0 + p * 8;
            tile[ty][tx] = affine_w[(i0 + ty) * NE + e0 + tx];
        }
        __syncthreads();
        #pragma unroll
        for (int p = 0; p < 4; p++) {
            int ty = ty0 + p * 8;
            float v = tile[tx][ty];
            __half h, l; split2(v, h, l);
            long base = (long)(e0 + ty) * 1536 + i0 + tx;
            g_AWT[base] = h; g_AWT[base + 512] = l; g_AWT[base + 1024] = h;
        }
    } else if (bid < PB_BCONST) {
        __shared__ float tile[32][33];
        int lb = bid - PB_SST;
        int b = lb >> 9;
        int rem = lb & 511;
        int dy = rem >> 5, sx = rem & 31;
        int s0 = sx * 32, d0 = dy * 32;
        int tx = tid & 31, ty0 = tid >> 5;
        #pragma unroll
        for (int p = 0; p < 4; p++) {
            int ty = ty0 + p * 8;
            tile[ty][tx] = src_seq[((long)b * NS + s0 + ty) * NC2 + d0 + tx];
        }
        __syncthreads();
        #pragma unroll
        for (int p = 0; p < 4; p++) {
            int ty = ty0 + p * 8;
            g_SST[((long)b * NC2 + d0 + ty) * NS + s0 + tx] = __float2half(tile[tx][ty]);
        }
    } else {
        int wid = (bid - PB_BCONST) * 8 + (tid >> 5);
        int lane = tid & 31;
        int tap = wid / 512, o = wid % 512;
        const float* row = conv_w + (long)o * 1536 + tap * 512;
        float s = 0.f;
        for (int i = lane; i < 512; i += 32) s += row[i] * affine_b[i];
        #pragma unroll
        for (int off = 16; off > 0; off >>= 1) s += __shfl_xor_sync(~0u, s, off);
        if (lane == 0) g_BC[tap * 512 + o] = s;
    }
}

// GLU: warp per row, zero smem / zero block barriers
__global__ void glu_kernel() {
    int wid = threadIdx.x >> 5;
    int m   = blockIdx.x * 8 + wid;
    int lane = threadIdx.x & 31;
    const uint4* yrow = (const uint4*)(g_Yh + (long)m * NC2);
    uint4 av = yrow[lane];
    uint4 gv = yrow[32 + lane];
    const __half2* ah = (const __half2*)&av;
    const __half2* gh = (const __half2*)&gv;
    float a[8], g[8];
    #pragma unroll
    for (int i = 0; i < 4; i++) {
        a[2*i]   = fmaxf(__low2float(ah[i]), 0.f);
        a[2*i+1] = fmaxf(__high2float(ah[i]), 0.f);
        g[2*i]   = fmaxf(__low2float(gh[i]), 0.f);
        g[2*i+1] = fmaxf(__high2float(gh[i]), 0.f);
    }
    float mx = g[0];
    #pragma unroll
    for (int i = 1; i < 8; i++) mx = fmaxf(mx, g[i]);
    #pragma unroll
    for (int o = 16; o > 0; o >>= 1) mx = fmaxf(mx, __shfl_xor_sync(~0u, mx, o));
    float e[8], sum = 0.f;
    #pragma unroll
    for (int i = 0; i < 8; i++) { e[i] = __expf(g[i] - mx); sum += e[i]; }
    #pragma unroll
    for (int o = 16; o > 0; o >>= 1) sum += __shfl_xor_sync(~0u, sum, o);
    float inv = 1.f / sum;
    uint4 dv;
    __half2* dh = (__half2*)&dv;
    #pragma unroll
    for (int i = 0; i < 4; i++) {
        dh[i].x = __float2half(a[2*i]   * e[2*i]   * inv);
        dh[i].y = __float2half(a[2*i+1] * e[2*i+1] * inv);
    }
    *(uint4*)(g_Dh + (long)m * NH + lane * 8) = dv;
}

// softmax: warp per row (1024 elems, 32/lane via 4 strided uint4), zero smem
__global__ void softmax_rows_kernel() {
    int wid = threadIdx.x >> 5;
    int m   = blockIdx.x * 8 + wid;
    int lane = threadIdx.x & 31;
    const uint4* row = (const uint4*)(g_SCh + (long)m * NS);
    uint4 v4[4];
    #pragma unroll
    for (int q = 0; q < 4; q++) v4[q] = row[lane + q * 32];
    float x[32];
    #pragma unroll
    for (int q = 0; q < 4; q++) {
        const __half2* ph = (const __half2*)&v4[q];
        #pragma unroll
        for (int i = 0; i < 4; i++) {
            x[q * 8 + 2*i]   = __low2float(ph[i]);
            x[q * 8 + 2*i+1] = __high2float(ph[i]);
        }
    }
    float mx = x[0];
    #pragma unroll
    for (int i = 1; i < 32; i++) mx = fmaxf(mx, x[i]);
    #pragma unroll
    for (int o = 16; o > 0; o >>= 1) mx = fmaxf(mx, __shfl_xor_sync(~0u, mx, o));
    float sum = 0.f;
    #pragma unroll
    for (int i = 0; i < 32; i++) { x[i] = __expf(x[i] - mx); sum += x[i]; }
    #pragma unroll
    for (int o = 16; o > 0; o >>= 1) sum += __shfl_xor_sync(~0u, sum, o);
    float inv = 1.f / sum;
    uint4* orow = (uint4*)(g_ATh + (long)m * NS);
    #pragma unroll
    for (int q = 0; q < 4; q++) {
        uint4 ov;
        __half2* oh = (__half2*)&ov;
        #pragma unroll
        for (int i = 0; i < 4; i++) {
            oh[i].x = __float2half(x[q * 8 + 2*i]   * inv);
            oh[i].y = __float2half(x[q * 8 + 2*i+1] * inv);
        }
        orow[lane + q * 32] = ov;
    }
}

// ---------------- mma.sync fp16 GEMM (R10: 256 thr, 2x4 warps, 64x32 tile) ---
#define GEMM_SMEM (4 * 16384)

template <int AMODE, int EPI, int NSEG, bool BCAT>
__global__ __launch_bounds__(256, 2)
void gemm_mma(const __half* __restrict__ Ahi, const __half* __restrict__ Alo, long aBatch,
              int KB, int lda, const __half* __restrict__ Bm, long bBatch,
              const __half* __restrict__ B2,
              const float* __restrict__ bias,
              float* __restrict__ C, int cLd,
              __half* __restrict__ Ohi, long oBatch,
              int Mb) {
    extern __shared__ char smem[];
    const uint32_t sb = smem_u32(smem);
    const int tid = threadIdx.x;
    const int z  = blockIdx.z;
    const int l0 = blockIdx.y * 128;
    const int n0 = blockIdx.x * 128;
    const int Kp = NSEG * KB;
    const int NK = Kp / 32;
    const __half* Bb = Bm + (long)z * bBatch;
    Ahi += (long)z * aBatch;
    if (NSEG == 3) Alo += (long)z * aBatch;

    auto load_tile = [&](int kt, int st) {
        const int k0 = kt * 32;
        const uint32_t sA = sb + st * 16384;
        const uint32_t sB = sA + 8192;
        {
            const int seg = (NSEG == 3) ? (k0 / KB) : 0;
            const int rem0 = (NSEG == 3) ? (k0 - seg * KB) : k0;
            #pragma unroll
            for (int i = 0; i < 2; i++) {
                int c = tid + i * 256;
                int m = c >> 2, kc = c & 3;
                int l = l0 + m;
                long g; bool ok; const __half* Ab;
                if (AMODE == 0) {
                    ok = (l < Mb);
                    long rowbase = aBatch ? (long)l : ((long)z * Mb + l);
                    g = rowbase * (long)lda + rem0 + kc * 8;
                    Ab = (NSEG == 3 && seg == 2) ? Alo : Ahi;
                } else if (AMODE == 2) {
                    int tap = rem0 >> 8;
                    int e = (rem0 & 255) + kc * 8;
                    int t = l - 2 + tap;
                    ok = (l < Mb) && (t >= 0);
                    g = ((long)z * 1024 + t) * 256 + e;
                    Ab = Ahi;
                } else {
                    ok = (l < Mb);
                    if (k0 < 256) { g = ((long)z * Mb + l) * 256 + k0 + kc * 8; Ab = Ahi; }
                    else          { g = ((long)z * Mb + l) * 1024 + (k0 - 256) + kc * 8; Ab = Alo; }
                }
                cpasync16(sA + m * 64 + ((uint32_t)(kc ^ (m & 3)) << 4), Ab + (ok ? g : 0), ok);
            }
        }
        #pragma unroll
        for (int i = 0; i < 2; i++) {
            int c = tid + i * 256;
            int n = c >> 2, kc = c & 3;
            const __half* src; long g;
            if (BCAT) {
                if (k0 < 256) { src = Bm; g = (long)(n0 + n) * 256 + k0 + kc * 8; }
                else { src = B2; g = ((long)z * 512 + n0 + n) * 1024 + (k0 - 256) + kc * 8; }
            } else {
                src = Bb; g = (long)(n0 + n) * Kp + k0 + kc * 8;
            }
            cpasync16(sB + n * 64 + ((uint32_t)(kc ^ (n & 3)) << 4), src + g, true);
        }
        cp_commit();
    };

    float acc[4][4][4];
    #pragma unroll
    for (int i = 0; i < 4; i++)
        #pragma unroll
        for (int j = 0; j < 4; j++)
            #pragma unroll
            for (int q = 0; q < 4; q++) acc[i][j][q] = 0.f;

    const int w = tid >> 5, lid = tid & 31;
    const int wm = w >> 2, wn = w & 3;
    const int rl = wm * 64 + (lid & 15);
    const int aC = lid >> 4;
    const int nl = wn * 32 + ((lid >> 4) << 3) + (lid & 7);
    const int bC = (lid >> 3) & 1;

    load_tile(0, 0); load_tile(1, 1); load_tile(2, 2);

    for (int kt = 0; kt < NK; kt++) {
        const int st = kt & 3;
        asm volatile("cp.async.wait_group 2;\n" ::: "memory");
        __syncthreads();
        if (kt + 3 < NK) load_tile(kt + 3, (kt + 3) & 3);
        else cp_commit();

        const uint32_t sA = sb + st * 16384;
        const uint32_t sB = sA + 8192;
        #pragma unroll
        for (int ks = 0; ks < 2; ks++) {
            uint32_t a[4][4];
            #pragma unroll
            for (int i = 0; i < 4; i++) {
                int r = rl + i * 16;
                ldm4(a[i], sA + r * 64 + ((uint32_t)((ks * 2 + aC) ^ (r & 3)) << 4));
            }
            uint32_t b[4][2];
            #pragma unroll
            for (int jj = 0; jj < 2; jj++) {
                int n = nl + jj * 16;
                uint32_t t[4];
                ldm4(t, sB + n * 64 + ((uint32_t)((ks * 2 + bC) ^ (n & 3)) << 4));
                b[jj * 2][0] = t[0]; b[jj * 2][1] = t[1];
                b[jj * 2 + 1][0] = t[2]; b[jj * 2 + 1][1] = t[3];
            }
            #pragma unroll
            for (int i = 0; i < 4; i++)
                #pragma unroll
                for (int j = 0; j < 4; j++)
                    mma16816(acc[i][j], a[i], b[j]);
        }
    }

    // ---------------- epilogue ----------------
    const int g  = lid >> 2, t4 = lid & 3;
    __half* Op = Ohi + (long)z * oBatch;
    #pragma unroll
    for (int i = 0; i < 4; i++) {
        #pragma unroll
        for (int h = 0; h < 2; h++) {
            int row = l0 + wm * 64 + i * 16 + g + h * 8;
            if (row >= Mb) continue;
            long grow = (long)z * Mb + row;
            long orow = oBatch ? (long)row : grow;
            #pragma unroll
            for (int j = 0; j < 4; j++) {
                int col = n0 + wn * 32 + j * 8 + 2 * t4;
                float v0 = acc[i][j][h * 2 + 0];
                float v1 = acc[i][j][h * 2 + 1];
                if (EPI == 0) { v0 += bias[col]; v1 += bias[col + 1]; }
                if (EPI == 5) {
                    float b0 = bias[col]     + g_BC[1024 + col];
                    float b1 = bias[col + 1] + g_BC[1024 + col + 1];
                    if (row >= 1) { b0 += g_BC[512 + col]; b1 += g_BC[512 + col + 1]; }
                    if (row >= 2) { b0 += g_BC[col];       b1 += g_BC[col + 1]; }
                    v0 += b0; v1 += b1;
                }
                if (EPI == 3 || EPI == 5) {
                    __half2 hh; hh.x = __float2half(v0); hh.y = __float2half(v1);
                    *(__half2*)(Op + orow * (long)cLd + col) = hh;
                } else {
                    float* cp = C + grow * (long)cLd + col;
                    float2 r; r.x = v0; r.y = v1;
                    *(float2*)cp = r;
                }
            }
        }
    }
}

// ---------------- launcher ---------------------------------------------------
extern "C" void kernel_launch(void* const* d_in, const int* in_sizes, int n_in,
                              void* d_out, int out_size) {
    const int*   target   = (const int*)d_in[1];
    const float* enc_attn = (const float*)d_in[2];
    const float* src_seq  = (const float*)d_in[3];
    const float* emb      = (const float*)d_in[4];
    const float* affine_w = (const float*)d_in[5];
    const float* affine_b = (const float*)d_in[6];
    const float* conv_w   = (const float*)d_in[7];
    const float* conv_b   = (const float*)d_in[8];
    const float* map_w    = (const float*)d_in[9];
    const float* map_b    = (const float*)d_in[10];
    float* out = (float*)d_out;

    __half *Gh, *Yh, *Dh, *SCh, *ATh, *CWh, *CWl, *AWT, *FWB, *MWb, *EAb, *SST;
    cudaGetSymbolAddress((void**)&Gh,  g_Gh);
    cudaGetSymbolAddress((void**)&Yh,  g_Yh);
    cudaGetSymbolAddress((void**)&Dh,  g_Dh);
    cudaGetSymbolAddress((void**)&SCh, g_SCh);
    cudaGetSymbolAddress((void**)&ATh, g_ATh);
    cudaGetSymbolAddress((void**)&CWh, g_CWh);   cudaGetSymbolAddress((void**)&CWl, g_CWl);
    cudaGetSymbolAddress((void**)&AWT, g_AWT);   cudaGetSymbolAddress((void**)&FWB, g_FWB);
    cudaGetSymbolAddress((void**)&MWb, g_MWb);   cudaGetSymbolAddress((void**)&EAb, g_EAb);
    cudaGetSymbolAddress((void**)&SST, g_SST);

    cudaFuncSetAttribute(gemm_mma<0, 3, 3, false>, cudaFuncAttributeMaxDynamicSharedMemorySize, GEMM_SMEM);
    cudaFuncSetAttribute(gemm_mma<2, 5, 1, false>, cudaFuncAttributeMaxDynamicSharedMemorySize, GEMM_SMEM);
    cudaFuncSetAttribute(gemm_mma<0, 3, 1, false>, cudaFuncAttributeMaxDynamicSharedMemorySize, GEMM_SMEM);
    cudaFuncSetAttribute(gemm_mma<3, 0, 1, true>,  cudaFuncAttributeMaxDynamicSharedMemorySize, GEMM_SMEM);

    // 1. all conversions / weight prep in one launch
    mega_prep<<<PB_TOTAL, 256>>>(target, emb, enc_attn, map_w, conv_w,
                                 affine_w, affine_b, src_seq);
    // 2. fused weight (3-term, batched over taps): FW_tap = conv_w[.,tap,:] @ AWT
    gemm_mma<0, 3, 3, false><<<dim3(2, 4, 3), 256, GEMM_SMEM>>>(
        CWh, CWl, 512, 512, 1536, AWT, 0, nullptr,
        nullptr, nullptr, 768, FWB, 256, 512);
    // 3. fused conv on G -> Yh fp16 (+conv bias folded in epilogue)
    gemm_mma<2, 5, 1, false><<<dim3(4, 8, NB), 256, GEMM_SMEM>>>(
        Gh, nullptr, 0, 768, 0, FWB, 0, nullptr, conv_b, nullptr, 512, Yh, 0, NL);
    // 4. GLU -> Dh (warp per row)
    glu_kernel<<<NM2 / 8, 256>>>();
    // 5. scores -> SCh fp16 (batched)  (N=1024, K=256)
    gemm_mma<0, 3, 1, false><<<dim3(8, 8, NB), 256, GEMM_SMEM>>>(
        Dh, nullptr, 0, 256, 256, EAb, (long)NS * NH, nullptr,
        nullptr, nullptr, NS, SCh, 0, NL);
    // 6. softmax -> ATh fp16 (warp per row)
    softmax_rows_kernel<<<NM2 / 8, 256>>>();
    // 7. combined: out = [Dh|ATh] @ [map_w|SST]^T + map_b   (N=512, K=1280)
    gemm_mma<3, 0, 1, true><<<dim3(4, 8, NB), 256, GEMM_SMEM>>>(
        Dh, ATh, 0, 1280, 0, MWb, 0, SST, map_b, out, 512, nullptr, 0, NL);
}

// round 17
// speedup vs baseline: 1.5756x; 1.2400x over previous
#include <cuda_runtime.h>
#include <cuda_fp16.h>
#include <cstdint>

#define NB   32
#define NL   1023
#define NS   1024
#define NH   256
#define NC2  512
#define NE   256
#define NM1  32768
#define NM2  32736

// swizzle: chunk position = x ^ ((row>>1)&3)  (conflict-free ldmatrix phases)
#define SWZ(row, x) ((uint32_t)((x) ^ (((row) >> 1) & 3)) << 4)

// ---------------- scratch ----------------------------------------------------
__device__ __half g_Gh [NM1 * NE];
__device__ __half g_Yh [NM2 * NC2];
__device__ __half g_Dh [NM2 * NH];
__device__ __half g_SCh[(long)NM2 * NS];
__device__ __half g_ATh[(long)NM2 * NS];
__device__ __half g_CWh[NC2 * 1536], g_CWl[NC2 * 1536];
__device__ __half g_AWT[NE * 3 * NC2];
__device__ __half g_FWB[NC2 * 768];
__device__ __half g_MWb[NC2 * NH];
__device__ __half g_EAb[(long)NB * NS * NH];
__device__ __half g_SST[(long)NB * NC2 * NS];
__device__ float  g_BC [3 * NC2];

// ---------------- helpers ----------------------------------------------------
__device__ __forceinline__ uint32_t smem_u32(const void* p) {
    uint32_t a;
    asm("{ .reg .u64 t; cvta.to.shared.u64 t, %1; cvt.u32.u64 %0, t; }" : "=r"(a) : "l"(p));
    return a;
}
__device__ __forceinline__ void cpasync16(uint32_t s, const void* g, bool pred) {
    int sz = pred ? 16 : 0;
    asm volatile("cp.async.cg.shared.global [%0], [%1], 16, %2;\n" :: "r"(s), "l"(g), "r"(sz));
}
__device__ __forceinline__ void cp_commit() { asm volatile("cp.async.commit_group;\n" ::: "memory"); }

__device__ __forceinline__ void ldm4(uint32_t* r, uint32_t a) {
    asm volatile("ldmatrix.sync.aligned.m8n8.x4.shared.b16 {%0,%1,%2,%3}, [%4];"
                 : "=r"(r[0]), "=r"(r[1]), "=r"(r[2]), "=r"(r[3]) : "r"(a));
}
__device__ __forceinline__ void mma16816(float* c, const uint32_t* a, const uint32_t* b) {
    asm volatile(
        "mma.sync.aligned.m16n8k16.row.col.f32.f16.f16.f32 "
        "{%0,%1,%2,%3}, {%4,%5,%6,%7}, {%8,%9}, {%0,%1,%2,%3};"
        : "+f"(c[0]), "+f"(c[1]), "+f"(c[2]), "+f"(c[3])
        : "r"(a[0]), "r"(a[1]), "r"(a[2]), "r"(a[3]), "r"(b[0]), "r"(b[1]));
}
__device__ __forceinline__ void split2(float v, __half& h, __half& l) {
    h = __float2half(v);
    l = __float2half(v - __half2float(h));
}
__device__ __forceinline__ uint2 pack4h(float a, float b, float c, float d) {
    __half2 lo; lo.x = __float2half(a); lo.y = __float2half(b);
    __half2 hi; hi.x = __float2half(c); hi.y = __float2half(d);
    uint2 r; r.x = *(uint32_t*)&lo; r.y = *(uint32_t*)&hi;
    return r;
}

// ---------------- mega prep kernel (float4 / 4 elems per thread) -------------
#define PB_GATHER 0
#define PB_ENC    8192
#define PB_MAP    16384
#define PB_SPLIT  16512
#define PB_AWT    17280
#define PB_SST    17408
#define PB_BCONST 33792
#define PB_TOTAL  33984

__global__ void mega_prep(const int* __restrict__ target,
                          const float* __restrict__ emb,
                          const float* __restrict__ enc_attn,
                          const float* __restrict__ map_w,
                          const float* __restrict__ conv_w,
                          const float* __restrict__ affine_w,
                          const float* __restrict__ affine_b,
                          const float* __restrict__ src_seq) {
    const int bid = blockIdx.x;
    const int tid = threadIdx.x;

    if (bid < PB_ENC) {
        long q = (long)(bid - PB_GATHER) * 256 + tid;
        int m = (int)(q >> 6);
        int k4 = (int)(q & 63);
        int b = m >> 10, t = m & 1023;
        int idx = target[t * NB + b];
        float4 v = *(const float4*)(emb + (long)idx * NE + k4 * 4);
        *(uint2*)(g_Gh + (long)m * NE + k4 * 4) = pack4h(v.x, v.y, v.z, v.w);
    } else if (bid < PB_MAP) {
        long q = (long)(bid - PB_ENC) * 256 + tid;
        float4 v = *(const float4*)(enc_attn + q * 4);
        *(uint2*)(g_EAb + q * 4) = pack4h(v.x, v.y, v.z, v.w);
    } else if (bid < PB_SPLIT) {
        long q = (long)(bid - PB_MAP) * 256 + tid;
        float4 v = *(const float4*)(map_w + q * 4);
        *(uint2*)(g_MWb + q * 4) = pack4h(v.x, v.y, v.z, v.w);
    } else if (bid < PB_AWT) {
        long q = (long)(bid - PB_SPLIT) * 256 + tid;
        float4 v = *(const float4*)(conv_w + q * 4);
        __half h0, l0, h1, l1, h2, l2, h3, l3;
        split2(v.x, h0, l0); split2(v.y, h1, l1);
        split2(v.z, h2, l2); split2(v.w, h3, l3);
        *(uint2*)(g_CWh + q * 4) = pack4h(__half2float(h0), __half2float(h1),
                                          __half2float(h2), __half2float(h3));
        *(uint2*)(g_CWl + q * 4) = pack4h(__half2float(l0), __half2float(l1),
                                          __half2float(l2), __half2float(l3));
    } else if (bid < PB_SST) {
        __shared__ float tile[32][33];
        int lb = bid - PB_AWT;
        int i0 = (lb >> 3) * 32, e0 = (lb & 7) * 32;
        int tx = tid & 31, ty0 = tid >> 5;
        #pragma unroll
        for (int p = 0; p < 4; p++) {
            int ty = ty0 + p * 8;
            tile[ty][tx] = affine_w[(i0 + ty) * NE + e0 + tx];
        }
        __syncthreads();
        #pragma unroll
        for (int p = 0; p < 4; p++) {
            int ty = ty0 + p * 8;
            float v = tile[tx][ty];
            __half h, l; split2(v, h, l);
            long base = (long)(e0 + ty) * 1536 + i0 + tx;
            g_AWT[base] = h; g_AWT[base + 512] = l; g_AWT[base + 1024] = h;
        }
    } else if (bid < PB_BCONST) {
        __shared__ float tile[32][33];
        int lb = bid - PB_SST;
        int b = lb >> 9;
        int rem = lb & 511;
        int dy = rem >> 5, sx = rem & 31;
        int s0 = sx * 32, d0 = dy * 32;
        int tx = tid & 31, ty0 = tid >> 5;
        #pragma unroll
        for (int p = 0; p < 4; p++) {
            int ty = ty0 + p * 8;
            tile[ty][tx] = src_seq[((long)b * NS + s0 + ty) * NC2 + d0 + tx];
        }
        __syncthreads();
        #pragma unroll
        for (int p = 0; p < 4; p++) {
            int ty = ty0 + p * 8;
            g_SST[((long)b * NC2 + d0 + ty) * NS + s0 + tx] = __float2half(tile[tx][ty]);
        }
    } else {
        int wid = (bid - PB_BCONST) * 8 + (tid >> 5);
        int lane = tid & 31;
        int tap = wid / 512, o = wid % 512;
        const float* row = conv_w + (long)o * 1536 + tap * 512;
        float s = 0.f;
        for (int i = lane; i < 512; i += 32) s += row[i] * affine_b[i];
        #pragma unroll
        for (int off = 16; off > 0; off >>= 1) s += __shfl_xor_sync(~0u, s, off);
        if (lane == 0) g_BC[tap * 512 + o] = s;
    }
}

// GLU: warp per row, zero smem / zero block barriers
__global__ void glu_kernel() {
    int wid = threadIdx.x >> 5;
    int m   = blockIdx.x * 8 + wid;
    int lane = threadIdx.x & 31;
    const uint4* yrow = (const uint4*)(g_Yh + (long)m * NC2);
    uint4 av = yrow[lane];
    uint4 gv = yrow[32 + lane];
    const __half2* ah = (const __half2*)&av;
    const __half2* gh = (const __half2*)&gv;
    float a[8], g[8];
    #pragma unroll
    for (int i = 0; i < 4; i++) {
        a[2*i]   = fmaxf(__low2float(ah[i]), 0.f);
        a[2*i+1] = fmaxf(__high2float(ah[i]), 0.f);
        g[2*i]   = fmaxf(__low2float(gh[i]), 0.f);
        g[2*i+1] = fmaxf(__high2float(gh[i]), 0.f);
    }
    float mx = g[0];
    #pragma unroll
    for (int i = 1; i < 8; i++) mx = fmaxf(mx, g[i]);
    #pragma unroll
    for (int o = 16; o > 0; o >>= 1) mx = fmaxf(mx, __shfl_xor_sync(~0u, mx, o));
    float e[8], sum = 0.f;
    #pragma unroll
    for (int i = 0; i < 8; i++) { e[i] = __expf(g[i] - mx); sum += e[i]; }
    #pragma unroll
    for (int o = 16; o > 0; o >>= 1) sum += __shfl_xor_sync(~0u, sum, o);
    float inv = 1.f / sum;
    uint4 dv;
    __half2* dh = (__half2*)&dv;
    #pragma unroll
    for (int i = 0; i < 4; i++) {
        dh[i].x = __float2half(a[2*i]   * e[2*i]   * inv);
        dh[i].y = __float2half(a[2*i+1] * e[2*i+1] * inv);
    }
    *(uint4*)(g_Dh + (long)m * NH + lane * 8) = dv;
}

// softmax: warp per row (1024 elems, 32/lane via 4 strided uint4), zero smem
__global__ void softmax_rows_kernel() {
    int wid = threadIdx.x >> 5;
    int m   = blockIdx.x * 8 + wid;
    int lane = threadIdx.x & 31;
    const uint4* row = (const uint4*)(g_SCh + (long)m * NS);
    uint4 v4[4];
    #pragma unroll
    for (int q = 0; q < 4; q++) v4[q] = row[lane + q * 32];
    float x[32];
    #pragma unroll
    for (int q = 0; q < 4; q++) {
        const __half2* ph = (const __half2*)&v4[q];
        #pragma unroll
        for (int i = 0; i < 4; i++) {
            x[q * 8 + 2*i]   = __low2float(ph[i]);
            x[q * 8 + 2*i+1] = __high2float(ph[i]);
        }
    }
    float mx = x[0];
    #pragma unroll
    for (int i = 1; i < 32; i++) mx = fmaxf(mx, x[i]);
    #pragma unroll
    for (int o = 16; o > 0; o >>= 1) mx = fmaxf(mx, __shfl_xor_sync(~0u, mx, o));
    float sum = 0.f;
    #pragma unroll
    for (int i = 0; i < 32; i++) { x[i] = __expf(x[i] - mx); sum += x[i]; }
    #pragma unroll
    for (int o = 16; o > 0; o >>= 1) sum += __shfl_xor_sync(~0u, sum, o);
    float inv = 1.f / sum;
    uint4* orow = (uint4*)(g_ATh + (long)m * NS);
    #pragma unroll
    for (int q = 0; q < 4; q++) {
        uint4 ov;
        __half2* oh = (__half2*)&ov;
        #pragma unroll
        for (int i = 0; i < 4; i++) {
            oh[i].x = __float2half(x[q * 8 + 2*i]   * inv);
            oh[i].y = __float2half(x[q * 8 + 2*i+1] * inv);
        }
        orow[lane + q * 32] = ov;
    }
}

// ---------------- mma.sync fp16 GEMM (256 thr, 2x4 warps, 64x32 warp tile) ---
#define GEMM_SMEM (4 * 16384)

template <int AMODE, int EPI, int NSEG, bool BCAT>
__global__ __launch_bounds__(256, 2)
void gemm_mma(const __half* __restrict__ Ahi, const __half* __restrict__ Alo, long aBatch,
              int KB, int lda, const __half* __restrict__ Bm, long bBatch,
              const __half* __restrict__ B2,
              const float* __restrict__ bias,
              float* __restrict__ C, int cLd,
              __half* __restrict__ Ohi, long oBatch,
              int Mb) {
    extern __shared__ char smem[];
    const uint32_t sb = smem_u32(smem);
    const int tid = threadIdx.x;
    const int z  = blockIdx.z;
    const int l0 = blockIdx.y * 128;
    const int n0 = blockIdx.x * 128;
    const int Kp = NSEG * KB;
    const int NK = Kp / 32;
    const __half* Bb = Bm + (long)z * bBatch;
    Ahi += (long)z * aBatch;
    if (NSEG == 3) Alo += (long)z * aBatch;

    auto load_tile = [&](int kt, int st) {
        const int k0 = kt * 32;
        const uint32_t sA = sb + st * 16384;
        const uint32_t sB = sA + 8192;
        {
            const int seg = (NSEG == 3) ? (k0 / KB) : 0;
            const int rem0 = (NSEG == 3) ? (k0 - seg * KB) : k0;
            #pragma unroll
            for (int i = 0; i < 2; i++) {
                int c = tid + i * 256;
                int m = c >> 2, kc = c & 3;
                int l = l0 + m;
                long g; bool ok; const __half* Ab;
                if (AMODE == 0) {
                    ok = (l < Mb);
                    long rowbase = aBatch ? (long)l : ((long)z * Mb + l);
                    g = rowbase * (long)lda + rem0 + kc * 8;
                    Ab = (NSEG == 3 && seg == 2) ? Alo : Ahi;
                } else if (AMODE == 2) {
                    int tap = rem0 >> 8;
                    int e = (rem0 & 255) + kc * 8;
                    int t = l - 2 + tap;
                    ok = (l < Mb) && (t >= 0);
                    g = ((long)z * 1024 + t) * 256 + e;
                    Ab = Ahi;
                } else {
                    ok = (l < Mb);
                    if (k0 < 256) { g = ((long)z * Mb + l) * 256 + k0 + kc * 8; Ab = Ahi; }
                    else          { g = ((long)z * Mb + l) * 1024 + (k0 - 256) + kc * 8; Ab = Alo; }
                }
                cpasync16(sA + m * 64 + SWZ(m, kc), Ab + (ok ? g : 0), ok);
            }
        }
        #pragma unroll
        for (int i = 0; i < 2; i++) {
            int c = tid + i * 256;
            int n = c >> 2, kc = c & 3;
            const __half* src; long g;
            if (BCAT) {
                if (k0 < 256) { src = Bm; g = (long)(n0 + n) * 256 + k0 + kc * 8; }
                else { src = B2; g = ((long)z * 512 + n0 + n) * 1024 + (k0 - 256) + kc * 8; }
            } else {
                src = Bb; g = (long)(n0 + n) * Kp + k0 + kc * 8;
            }
            cpasync16(sB + n * 64 + SWZ(n, kc), src + g, true);
        }
        cp_commit();
    };

    float acc[4][4][4];
    #pragma unroll
    for (int i = 0; i < 4; i++)
        #pragma unroll
        for (int j = 0; j < 4; j++)
            #pragma unroll
            for (int q = 0; q < 4; q++) acc[i][j][q] = 0.f;

    const int w = tid >> 5, lid = tid & 31;
    const int wm = w >> 2, wn = w & 3;
    const int rl = wm * 64 + (lid & 15);
    const int aC = lid >> 4;
    const int nl = wn * 32 + ((lid >> 4) << 3) + (lid & 7);
    const int bC = (lid >> 3) & 1;

    load_tile(0, 0); load_tile(1, 1); load_tile(2, 2);

    for (int kt = 0; kt < NK; kt++) {
        const int st = kt & 3;
        asm volatile("cp.async.wait_group 2;\n" ::: "memory");
        __syncthreads();
        if (kt + 3 < NK) load_tile(kt + 3, (kt + 3) & 3);
        else cp_commit();

        const uint32_t sA = sb + st * 16384;
        const uint32_t sB = sA + 8192;
        #pragma unroll
        for (int ks = 0; ks < 2; ks++) {
            uint32_t a[4][4];
            #pragma unroll
            for (int i = 0; i < 4; i++) {
                int r = rl + i * 16;
                ldm4(a[i], sA + r * 64 + SWZ(r, ks * 2 + aC));
            }
            uint32_t b[4][2];
            #pragma unroll
            for (int jj = 0; jj < 2; jj++) {
                int n = nl + jj * 16;
                uint32_t t[4];
                ldm4(t, sB + n * 64 + SWZ(n, ks * 2 + bC));
                b[jj * 2][0] = t[0]; b[jj * 2][1] = t[1];
                b[jj * 2 + 1][0] = t[2]; b[jj * 2 + 1][1] = t[3];
            }
            #pragma unroll
            for (int i = 0; i < 4; i++)
                #pragma unroll
                for (int j = 0; j < 4; j++)
                    mma16816(acc[i][j], a[i], b[j]);
        }
    }

    // ---------------- epilogue ----------------
    const int g  = lid >> 2, t4 = lid & 3;
    __half* Op = Ohi + (long)z * oBatch;
    #pragma unroll
    for (int i = 0; i < 4; i++) {
        #pragma unroll
        for (int h = 0; h < 2; h++) {
            int row = l0 + wm * 64 + i * 16 + g + h * 8;
            if (row >= Mb) continue;
            long grow = (long)z * Mb + row;
            long orow = oBatch ? (long)row : grow;
            #pragma unroll
            for (int j = 0; j < 4; j++) {
                int col = n0 + wn * 32 + j * 8 + 2 * t4;
                float v0 = acc[i][j][h * 2 + 0];
                float v1 = acc[i][j][h * 2 + 1];
                if (EPI == 0) { v0 += bias[col]; v1 += bias[col + 1]; }
                if (EPI == 5) {
                    float b0 = bias[col]     + g_BC[1024 + col];
                    float b1 = bias[col + 1] + g_BC[1024 + col + 1];
                    if (row >= 1) { b0 += g_BC[512 + col]; b1 += g_BC[512 + col + 1]; }
                    if (row >= 2) { b0 += g_BC[col];       b1 += g_BC[col + 1]; }
                    v0 += b0; v1 += b1;
                }
                if (EPI == 3 || EPI == 5) {
                    __half2 hh; hh.x = __float2half(v0); hh.y = __float2half(v1);
                    *(__half2*)(Op + orow * (long)cLd + col) = hh;
                } else {
                    float* cp = C + grow * (long)cLd + col;
                    float2 r; r.x = v0; r.y = v1;
                    *(float2*)cp = r;
                }
            }
        }
    }
}

// ---------------- launcher ---------------------------------------------------
extern "C" void kernel_launch(void* const* d_in, const int* in_sizes, int n_in,
                              void* d_out, int out_size) {
    const int*   target   = (const int*)d_in[1];
    const float* enc_attn = (const float*)d_in[2];
    const float* src_seq  = (const float*)d_in[3];
    const float* emb      = (const float*)d_in[4];
    const float* affine_w = (const float*)d_in[5];
    const float* affine_b = (const float*)d_in[6];
    const float* conv_w   = (const float*)d_in[7];
    const float* conv_b   = (const float*)d_in[8];
    const float* map_w    = (const float*)d_in[9];
    const float* map_b    = (const float*)d_in[10];
    float* out = (float*)d_out;

    __half *Gh, *Yh, *Dh, *SCh, *ATh, *CWh, *CWl, *AWT, *FWB, *MWb, *EAb, *SST;
    cudaGetSymbolAddress((void**)&Gh,  g_Gh);
    cudaGetSymbolAddress((void**)&Yh,  g_Yh);
    cudaGetSymbolAddress((void**)&Dh,  g_Dh);
    cudaGetSymbolAddress((void**)&SCh, g_SCh);
    cudaGetSymbolAddress((void**)&ATh, g_ATh);
    cudaGetSymbolAddress((void**)&CWh, g_CWh);   cudaGetSymbolAddress((void**)&CWl, g_CWl);
    cudaGetSymbolAddress((void**)&AWT, g_AWT);   cudaGetSymbolAddress((void**)&FWB, g_FWB);
    cudaGetSymbolAddress((void**)&MWb, g_MWb);   cudaGetSymbolAddress((void**)&EAb, g_EAb);
    cudaGetSymbolAddress((void**)&SST, g_SST);

    cudaFuncSetAttribute(gemm_mma<0, 3, 3, false>, cudaFuncAttributeMaxDynamicSharedMemorySize, GEMM_SMEM);
    cudaFuncSetAttribute(gemm_mma<2, 5, 1, false>, cudaFuncAttributeMaxDynamicSharedMemorySize, GEMM_SMEM);
    cudaFuncSetAttribute(gemm_mma<0, 3, 1, false>, cudaFuncAttributeMaxDynamicSharedMemorySize, GEMM_SMEM);
    cudaFuncSetAttribute(gemm_mma<3, 0, 1, true>,  cudaFuncAttributeMaxDynamicSharedMemorySize, GEMM_SMEM);

    // 1. all conversions / weight prep in one launch
    mega_prep<<<PB_TOTAL, 256>>>(target, emb, enc_attn, map_w, conv_w,
                                 affine_w, affine_b, src_seq);
    // 2. fused weight (3-term, batched over taps): FW_tap = conv_w[.,tap,:] @ AWT
    gemm_mma<0, 3, 3, false><<<dim3(2, 4, 3), 256, GEMM_SMEM>>>(
        CWh, CWl, 512, 512, 1536, AWT, 0, nullptr,
        nullptr, nullptr, 768, FWB, 256, 512);
    // 3. fused conv on G -> Yh fp16 (+conv bias folded in epilogue)
    gemm_mma<2, 5, 1, false><<<dim3(4, 8, NB), 256, GEMM_SMEM>>>(
        Gh, nullptr, 0, 768, 0, FWB, 0, nullptr, conv_b, nullptr, 512, Yh, 0, NL);
    // 4. GLU -> Dh (warp per row)
    glu_kernel<<<NM2 / 8, 256>>>();
    // 5. scores -> SCh fp16 (batched)  (N=1024, K=256)
    gemm_mma<0, 3, 1, false><<<dim3(8, 8, NB), 256, GEMM_SMEM>>>(
        Dh, nullptr, 0, 256, 256, EAb, (long)NS * NH, nullptr,
        nullptr, nullptr, NS, SCh, 0, NL);
    // 6. softmax -> ATh fp16 (warp per row)
    softmax_rows_kernel<<<NM2 / 8, 256>>>();
    // 7. combined: out = [Dh|ATh] @ [map_w|SST]^T + map_b   (N=512, K=1280)
    gemm_mma<3, 0, 1, true><<<dim3(4, 8, NB), 256, GEMM_SMEM>>>(
        Dh, ATh, 0, 1280, 0, MWb, 0, SST, map_b, out, 512, nullptr, 0, NL);
}